// round 4
// baseline (speedup 1.0000x reference)
#include <cuda_runtime.h>
#include <math.h>

typedef unsigned long long ull;

#define NN 50000
#define NE 1600000
#define PAD 130

#define A_SZ (144 * PAD)
#define B_SZ (128 * PAD)
#define W_SZ 18432
#define SM_FLOATS (A_SZ + B_SZ + W_SZ + 512)
#define SM_BYTES (SM_FLOATS * 4)

#define NTHR 512

__device__ float g_nf1[NN * 32];
__device__ float g_nf2[NN * 32];

// ---------- packed fp32x2 helpers (sm_103a FFMA2 pipe) ----------
__device__ __forceinline__ void fma2(ull &c, ull a, ull b) {
    asm("fma.rn.f32x2 %0, %1, %2, %0;" : "+l"(c) : "l"(a), "l"(b));
}
__device__ __forceinline__ ull packf2(float lo, float hi) {
    ull r; asm("mov.b64 %0, {%1, %2};" : "=l"(r) : "f"(lo), "f"(hi)); return r;
}
__device__ __forceinline__ float2 unpackf2(ull v) {
    float2 r; asm("mov.b64 {%0, %1}, %2;" : "=f"(r.x), "=f"(r.y) : "l"(v)); return r;
}

__device__ __forceinline__ void atomicMaxF(float* a, float v) {
    if (v >= 0.f) atomicMax((int*)a, __float_as_int(v));
    else          atomicMin((unsigned int*)a, (unsigned int)__float_as_int(v));
}

// stage weights [K][N] global -> smem duplicated [K][2N]: (w0,w0,w1,w1,...)
__device__ __forceinline__ void stageWdup(float* Wd, const float* __restrict__ Wg,
                                          int n, int t) {
    const float2* s = (const float2*)Wg;
    float4* d = (float4*)Wd;
    for (int i = t; i < n / 2; i += NTHR) {
        float2 w = s[i];
        d[i] = make_float4(w.x, w.x, w.y, w.y);
    }
}

// C[m][n] = sum_k A[k][m]*W[k][n] + bias[n].  A/C feature-major, stride PAD.
// 512 thr = 16 warps: warp&1 -> m-half (0/64), warp>>1 -> n-group of NT.
// Lane covers m-pair {mh+2l, mh+2l+1}. Wd duplicated [K][2N]. N % NT == 0, NT even.
template<int K, int N, int NT, bool RELU>
__device__ __forceinline__ void gemm2(const float* A, const float* Wd,
                                      const float* __restrict__ bias, float* C, int t) {
    const int warp = t >> 5, lane = t & 31;
    const int tm2 = ((warp & 1) << 6) + 2 * lane;
    const int n0 = (warp >> 1) * NT;
    ull acc[NT];
#pragma unroll
    for (int j = 0; j < NT; j++) {
        float b = bias[n0 + j];
        acc[j] = packf2(b, b);
    }
#pragma unroll 4
    for (int k = 0; k < K; k++) {
        ull a = *(const ull*)(A + k * PAD + tm2);
        const ull* wr = (const ull*)(Wd + k * 2 * N) + n0;
#pragma unroll
        for (int j = 0; j < NT; j += 2) {
            ulonglong2 w = *(const ulonglong2*)(wr + j);
            fma2(acc[j],     a, w.x);
            fma2(acc[j + 1], a, w.y);
        }
    }
#pragma unroll
    for (int j = 0; j < NT; j++) {
        float2 v = unpackf2(acc[j]);
        if (RELU) { v.x = fmaxf(v.x, 0.2f * v.x); v.y = fmaxf(v.y, 0.2f * v.y); }
        *(float2*)(C + (n0 + j) * PAD + tm2) = v;
    }
}

extern "C" __global__ void __launch_bounds__(NTHR)
edge_kernel(const float* __restrict__ nf, const float* __restrict__ ef,
            const int* __restrict__ src, const int* __restrict__ dst,
            const float* __restrict__ Wm1, const float* __restrict__ bm1,
            const float* __restrict__ Wm2, const float* __restrict__ bm2,
            const float* __restrict__ Wm3, const float* __restrict__ bm3,
            const float* __restrict__ Wm4, const float* __restrict__ bm4) {
    extern __shared__ float sm[];
    float* A  = sm;
    float* B  = sm + A_SZ;
    float* Ws = sm + A_SZ + B_SZ;
    int*  sidx = (int*)(sm + A_SZ + B_SZ + W_SZ);
    float* sg   = sm + A_SZ + B_SZ + W_SZ + 256;
    float* gcol = sm + A_SZ + B_SZ + W_SZ + 384;

    const int t = threadIdx.x;
    const int wid = t >> 5, lane = t & 31;
    const int e0 = blockIdx.x * 128;

    if (t < 128)      sidx[t] = src[e0 + t];
    else if (t < 256) sidx[t] = dst[e0 + t - 128];
    __syncthreads();

    // gather: X = [nf[src] | nf[dst] | ef] -> A feature-major [144][PAD]
    for (int m = wid; m < 128; m += 16) {
        int s = sidx[m];
        A[lane * PAD + m]        = nf[s * 64 + lane];
        A[(lane + 32) * PAD + m] = nf[s * 64 + 32 + lane];
        int d = sidx[128 + m];
        A[(64 + lane) * PAD + m] = nf[d * 64 + lane];
        A[(96 + lane) * PAD + m] = nf[d * 64 + 32 + lane];
        if (lane < 16) A[(128 + lane) * PAD + m] = ef[(e0 + m) * 16 + lane];
    }
    __syncthreads();

    stageWdup(Ws, Wm1, 144 * 64, t);  __syncthreads();
    gemm2<144, 64, 8, true>(A, Ws, bm1, B, t);  __syncthreads();
    stageWdup(Ws, Wm2, 64 * 128, t);  __syncthreads();
    gemm2<64, 128, 16, true>(B, Ws, bm2, A, t); __syncthreads();
    stageWdup(Ws, Wm3, 128 * 64, t);  __syncthreads();
    gemm2<128, 64, 8, true>(A, Ws, bm3, B, t);  __syncthreads();

    // stage layer-4 weights: gate column -> gcol, columns 1..64 duplicated -> Ws
    for (int idx = t; idx < 64 * 65; idx += NTHR) {
        int k = idx / 65, j = idx - k * 65;
        float w = Wm4[idx];
        if (j == 0) gcol[k] = w;
        else { Ws[k * 128 + 2 * (j - 1)] = w; Ws[k * 128 + 2 * j - 1] = w; }
    }
    __syncthreads();

    // gated features (cols 1..64 of layer 4) -> A rows 0..63
    gemm2<64, 64, 8, false>(B, Ws, bm4 + 1, A, t);
    // gate column: g[m] = sigmoid(bm4[0] + sum_k B[k][m] * gcol[k])
    if (t < 128) {
        float s = bm4[0];
#pragma unroll 8
        for (int k = 0; k < 64; k++) s = fmaf(B[k * PAD + t], gcol[k], s);
        sg[t] = 1.f / (1.f + expf(-s));
    }
    __syncthreads();

    // scatter: A rows 0..31 -> atomic sum, rows 32..63 -> atomic max
    for (int idx = t; idx < 128 * 32; idx += NTHR) {
        int m = idx >> 5, h = idx & 31;
        float g = sg[m];
        int d = sidx[128 + m];
        atomicAdd(&g_nf1[d * 32 + h], A[h * PAD + m] * g);
        atomicMaxF(&g_nf2[d * 32 + h], A[(32 + h) * PAD + m] * g);
    }
}

extern "C" __global__ void __launch_bounds__(NTHR)
node_kernel(const float* __restrict__ nf,
            const float* __restrict__ Wr1, const float* __restrict__ br1,
            const float* __restrict__ Wr2, const float* __restrict__ br2,
            const float* __restrict__ Wr3, const float* __restrict__ br3,
            const float* __restrict__ Wr4, const float* __restrict__ br4,
            float* __restrict__ out) {
    extern __shared__ float sm[];
    float* A  = sm;
    float* B  = sm + A_SZ;
    float* Ws = sm + A_SZ + B_SZ;

    const int t = threadIdx.x;
    const int wid = t >> 5, lane = t & 31;
    const int n0 = blockIdx.x * 128;
    const int cnt = min(128, NN - n0);

    for (int m = wid; m < 128; m += 16) {
        int nd = n0 + min(m, cnt - 1);   // clamp: dup rows beyond cnt (ignored at store)
        A[lane * PAD + m]        = nf[nd * 64 + lane];
        A[(lane + 32) * PAD + m] = nf[nd * 64 + 32 + lane];
        A[(64 + lane) * PAD + m] = g_nf1[nd * 32 + lane];
        float v = g_nf2[nd * 32 + lane];
        A[(96 + lane) * PAD + m] = isfinite(v) ? v : 0.f;
    }
    __syncthreads();

    stageWdup(Ws, Wr1, 128 * 64, t);  __syncthreads();
    gemm2<128, 64, 8, true>(A, Ws, br1, B, t);  __syncthreads();
    stageWdup(Ws, Wr2, 64 * 128, t);  __syncthreads();
    gemm2<64, 128, 16, true>(B, Ws, br2, A, t); __syncthreads();
    stageWdup(Ws, Wr3, 128 * 64, t);  __syncthreads();
    gemm2<128, 64, 8, true>(A, Ws, br3, B, t);  __syncthreads();
    stageWdup(Ws, Wr4, 64 * 64, t);   __syncthreads();
    gemm2<64, 64, 8, false>(B, Ws, br4, A, t);  __syncthreads();

    for (int idx = t; idx < 128 * 64; idx += NTHR) {
        int m = idx >> 6, n = idx & 63;
        if (m < cnt) out[(n0 + m) * 64 + n] = A[n * PAD + m];
    }
}

extern "C" __global__ void init1_kernel() {
    int i = blockIdx.x * blockDim.x + threadIdx.x;
    if (i < NN * 32) g_nf1[i] = 0.f;
}
extern "C" __global__ void init2_kernel() {
    int i = blockIdx.x * blockDim.x + threadIdx.x;
    if (i < NN * 32) g_nf2[i] = -INFINITY;
}

extern "C" void kernel_launch(void* const* d_in, const int* in_sizes, int n_in,
                              void* d_out, int out_size) {
    (void)in_sizes; (void)n_in; (void)out_size;
    const float* nf = (const float*)d_in[0];
    const float* ef = (const float*)d_in[1];
    const int* src  = (const int*)d_in[2];
    const int* dst  = (const int*)d_in[3];

    cudaFuncSetAttribute(edge_kernel, cudaFuncAttributeMaxDynamicSharedMemorySize, SM_BYTES);
    cudaFuncSetAttribute(node_kernel, cudaFuncAttributeMaxDynamicSharedMemorySize, SM_BYTES);

    init1_kernel<<<(NN * 32 + 255) / 256, 256>>>();
    init2_kernel<<<(NN * 32 + 255) / 256, 256>>>();

    edge_kernel<<<NE / 128, NTHR, SM_BYTES>>>(
        nf, ef, src, dst,
        (const float*)d_in[4], (const float*)d_in[5],
        (const float*)d_in[6], (const float*)d_in[7],
        (const float*)d_in[8], (const float*)d_in[9],
        (const float*)d_in[10], (const float*)d_in[11]);

    node_kernel<<<(NN + 127) / 128, NTHR, SM_BYTES>>>(
        nf,
        (const float*)d_in[12], (const float*)d_in[13],
        (const float*)d_in[14], (const float*)d_in[15],
        (const float*)d_in[16], (const float*)d_in[17],
        (const float*)d_in[18], (const float*)d_in[19],
        (float*)d_out);
}

// round 6
// speedup vs baseline: 1.1932x; 1.1932x over previous
#include <cuda_runtime.h>
#include <cuda_fp16.h>
#include <mma.h>
#include <math.h>
#include <stdint.h>

using namespace nvcuda;

#define NN 50000
#define NE 1600000
#define NTHR 256

// ---------------- device scratch ----------------
__device__ float g_nf1[NN * 32];
__device__ float g_nf2[NN * 32];

// fp16 split weight images, [N][K] row-major, hi then lo contiguous per layer.
// offsets/sizes in halves
#define W_E1 0
#define S_E1 9216    // 64 x 144
#define W_E2 18432
#define S_E2 8192    // 128 x 64
#define W_E3 34816
#define S_E3 8192    // 64 x 128
#define W_E4 51200
#define S_E4 5120    // 80 x 64 (col0 = gate, 1..64 feats, 65..79 zero)
#define W_N1 61440
#define S_N1 8192    // 64 x 128
#define W_N2 77824
#define S_N2 8192    // 128 x 64
#define W_N3 94208
#define S_N3 8192    // 64 x 128
#define W_N4 110592
#define S_N4 4096    // 64 x 64
#define W_TOT 118784
__device__ __align__(16) __half g_w[W_TOT];

// ---------------- smem layout (bytes) ----------------
#define ACT_LD 160
#define C_LD   136
#define S_ACTH 0                 // 40960 = 128*160*2
#define S_ACTL 40960
#define S_C32  81920             // 69632 = 128*136*4
#define S_W    151552            // up to 36864
#define S_SRC  188416            // 512
#define S_DST  188928            // 512
#define S_G    189440            // 512
#define SMEM_B 189952

__device__ __forceinline__ void atomicMaxF(float* a, float v) {
    if (v >= 0.f) atomicMax((int*)a, __float_as_int(v));
    else          atomicMin((unsigned int*)a, (unsigned int)__float_as_int(v));
}

__device__ __forceinline__ void split_h(float v, __half& hi, __half& lo) {
    hi = __float2half_rn(v);
    lo = __float2half_rn(v - __half2float(hi));
}

// write 8 consecutive split halves at act[m][k0..k0+7]
__device__ __forceinline__ void store_split8(__half* aH, __half* aL, int m, int k0,
                                             const float* v) {
    __half h[8], l[8];
#pragma unroll
    for (int j = 0; j < 8; j++) split_h(v[j], h[j], l[j]);
    *(uint4*)(aH + m * ACT_LD + k0) = *(const uint4*)h;
    *(uint4*)(aL + m * ACT_LD + k0) = *(const uint4*)l;
}

__device__ __forceinline__ void stageW(__half* dst, const __half* src, int halves, int t) {
    for (int i = t * 8; i < halves; i += NTHR * 8)
        *(uint4*)(dst + i) = *(const uint4*)(src + i);
}

__device__ __forceinline__ void ld8(float* v, const float* p) {
    float4 a = *(const float4*)p, b = *(const float4*)(p + 4);
    v[0] = a.x; v[1] = a.y; v[2] = a.z; v[3] = a.w;
    v[4] = b.x; v[5] = b.y; v[6] = b.z; v[7] = b.w;
}

// ---------------- wmma layer ----------------
// C[128][N] = act[128][K] x W[N][K]^T  (fp16 split x3, fp32 acc) -> C32 stage
// 8 warps: warp&3 -> 32-row m-group; warp>>2 -> n-tile parity (interleaved)
template<int K, int N>
__device__ __forceinline__ void mma_layer(const __half* actH, const __half* actL,
                                          const __half* WH, const __half* WL,
                                          float* C32, int warp) {
    constexpr int NT = N / 16;
    constexpr int MX = (NT + 1) / 2;
    const int m0 = (warp & 3) * 32;
    const int nh = warp >> 2;

    wmma::fragment<wmma::accumulator, 16, 16, 16, float> acc[2][MX];
#pragma unroll
    for (int i = 0; i < MX; i++)
        if (nh + 2 * i < NT) {
            wmma::fill_fragment(acc[0][i], 0.f);
            wmma::fill_fragment(acc[1][i], 0.f);
        }

#pragma unroll 1
    for (int k0 = 0; k0 < K; k0 += 16) {
        wmma::fragment<wmma::matrix_a, 16, 16, 16, __half, wmma::row_major> aH0, aH1, aL0, aL1;
        wmma::load_matrix_sync(aH0, actH + m0 * ACT_LD + k0, ACT_LD);
        wmma::load_matrix_sync(aH1, actH + (m0 + 16) * ACT_LD + k0, ACT_LD);
        wmma::load_matrix_sync(aL0, actL + m0 * ACT_LD + k0, ACT_LD);
        wmma::load_matrix_sync(aL1, actL + (m0 + 16) * ACT_LD + k0, ACT_LD);
#pragma unroll
        for (int i = 0; i < MX; i++) {
            const int nt = nh + 2 * i;
            if (nt < NT) {
                wmma::fragment<wmma::matrix_b, 16, 16, 16, __half, wmma::col_major> bH, bL;
                wmma::load_matrix_sync(bH, WH + nt * 16 * K + k0, K);
                wmma::load_matrix_sync(bL, WL + nt * 16 * K + k0, K);
                wmma::mma_sync(acc[0][i], aH0, bH, acc[0][i]);
                wmma::mma_sync(acc[1][i], aH1, bH, acc[1][i]);
                wmma::mma_sync(acc[0][i], aH0, bL, acc[0][i]);
                wmma::mma_sync(acc[1][i], aH1, bL, acc[1][i]);
                wmma::mma_sync(acc[0][i], aL0, bH, acc[0][i]);
                wmma::mma_sync(acc[1][i], aL1, bH, acc[1][i]);
            }
        }
    }
#pragma unroll
    for (int i = 0; i < MX; i++) {
        const int nt = nh + 2 * i;
        if (nt < NT) {
            wmma::store_matrix_sync(C32 + m0 * C_LD + nt * 16, acc[0][i], C_LD,
                                    wmma::mem_row_major);
            wmma::store_matrix_sync(C32 + (m0 + 16) * C_LD + nt * 16, acc[1][i], C_LD,
                                    wmma::mem_row_major);
        }
    }
}

// bias + leaky relu + split -> act buffers
template<int N, bool RELU>
__device__ __forceinline__ void epi(const float* C32, const float* __restrict__ bias,
                                    __half* aH, __half* aL, int t) {
    for (int idx = t; idx < 128 * N / 8; idx += NTHR) {
        int m = idx / (N / 8), q = idx - m * (N / 8);
        int n = q * 8;
        float v[8];
#pragma unroll
        for (int j = 0; j < 8; j++) {
            float x = C32[m * C_LD + n + j] + bias[n + j];
            if (RELU) x = fmaxf(x, 0.2f * x);
            v[j] = x;
        }
        store_split8(aH, aL, m, n, v);
    }
}

// ---------------- prep / init ----------------
__device__ __forceinline__ void fill_img(int tid, int stride, int base, int S,
                                         const float* __restrict__ W,
                                         int Kr, int Nr, int Kp, int Np) {
    for (int i = tid; i < Np * Kp; i += stride) {
        int n = i / Kp, k = i - n * Kp;
        float v = (k < Kr && n < Nr) ? W[k * Nr + n] : 0.f;
        __half hi, lo;
        split_h(v, hi, lo);
        g_w[base + i] = hi;
        g_w[base + S + i] = lo;
    }
}

extern "C" __global__ void prep_kernel(const float* Wm1, const float* Wm2,
                                       const float* Wm3, const float* Wm4,
                                       const float* Wr1, const float* Wr2,
                                       const float* Wr3, const float* Wr4) {
    int tid = blockIdx.x * blockDim.x + threadIdx.x;
    int stride = gridDim.x * blockDim.x;
    fill_img(tid, stride, W_E1, S_E1, Wm1, 144, 64, 144, 64);
    fill_img(tid, stride, W_E2, S_E2, Wm2, 64, 128, 64, 128);
    fill_img(tid, stride, W_E3, S_E3, Wm3, 128, 64, 128, 64);
    fill_img(tid, stride, W_E4, S_E4, Wm4, 64, 65, 64, 80);
    fill_img(tid, stride, W_N1, S_N1, Wr1, 128, 64, 128, 64);
    fill_img(tid, stride, W_N2, S_N2, Wr2, 64, 128, 64, 128);
    fill_img(tid, stride, W_N3, S_N3, Wr3, 128, 64, 128, 64);
    fill_img(tid, stride, W_N4, S_N4, Wr4, 64, 64, 64, 64);
}

extern "C" __global__ void init1_kernel() {
    int i = blockIdx.x * blockDim.x + threadIdx.x;
    if (i < NN * 32) g_nf1[i] = 0.f;
}
extern "C" __global__ void init2_kernel() {
    int i = blockIdx.x * blockDim.x + threadIdx.x;
    if (i < NN * 32) g_nf2[i] = -INFINITY;
}

// ---------------- edge kernel ----------------
extern "C" __global__ void __launch_bounds__(NTHR)
edge_kernel(const float* __restrict__ nf, const float* __restrict__ ef,
            const int* __restrict__ src, const int* __restrict__ dst,
            const float* __restrict__ bm1, const float* __restrict__ bm2,
            const float* __restrict__ bm3, const float* __restrict__ bm4) {
    extern __shared__ char smemc[];
    __half* aH  = (__half*)(smemc + S_ACTH);
    __half* aL  = (__half*)(smemc + S_ACTL);
    float*  C32 = (float*)(smemc + S_C32);
    __half* Wb  = (__half*)(smemc + S_W);
    int* ssrc = (int*)(smemc + S_SRC);
    int* sdst = (int*)(smemc + S_DST);
    float* sg = (float*)(smemc + S_G);

    const int t = threadIdx.x, warp = t >> 5;
    const int e0 = blockIdx.x * 128;

    if (t < 128) { ssrc[t] = src[e0 + t]; sdst[t] = dst[e0 + t]; }
    __syncthreads();

    // gather X = [nf[src] | nf[dst] | ef] -> split act tiles, K = 144
    for (int idx = t; idx < 128 * 18; idx += NTHR) {
        int m = idx / 18, g = idx - m * 18;
        float v[8];
        if (g < 8)       ld8(v, nf + (size_t)ssrc[m] * 64 + g * 8);
        else if (g < 16) ld8(v, nf + (size_t)sdst[m] * 64 + (g - 8) * 8);
        else             ld8(v, ef + (size_t)(e0 + m) * 16 + (g - 16) * 8);
        store_split8(aH, aL, m, g * 8, v);
    }
    stageW(Wb, g_w + W_E1, 2 * S_E1, t);
    __syncthreads();

    mma_layer<144, 64>(aH, aL, Wb, Wb + S_E1, C32, warp);
    __syncthreads();
    epi<64, true>(C32, bm1, aH, aL, t);
    stageW(Wb, g_w + W_E2, 2 * S_E2, t);
    __syncthreads();

    mma_layer<64, 128>(aH, aL, Wb, Wb + S_E2, C32, warp);
    __syncthreads();
    epi<128, true>(C32, bm2, aH, aL, t);
    stageW(Wb, g_w + W_E3, 2 * S_E3, t);
    __syncthreads();

    mma_layer<128, 64>(aH, aL, Wb, Wb + S_E3, C32, warp);
    __syncthreads();
    epi<64, true>(C32, bm3, aH, aL, t);
    stageW(Wb, g_w + W_E4, 2 * S_E4, t);
    __syncthreads();

    mma_layer<64, 80>(aH, aL, Wb, Wb + S_E4, C32, warp);
    __syncthreads();

    // gate
    if (t < 128) sg[t] = 1.f / (1.f + expf(-(C32[t * C_LD] + bm4[0])));
    __syncthreads();

    // scatter: feats 0..31 -> sum, 32..63 -> max (C32 cols 1..64)
    for (int idx = t; idx < 8192; idx += NTHR) {
        int h = idx >> 7, m = idx & 127;
        float val = (C32[m * C_LD + 1 + h] + bm4[1 + h]) * sg[m];
        int d = sdst[m];
        if (h < 32) atomicAdd(&g_nf1[d * 32 + h], val);
        else        atomicMaxF(&g_nf2[d * 32 + (h - 32)], val);
    }
}

// ---------------- node kernel ----------------
extern "C" __global__ void __launch_bounds__(NTHR)
node_kernel(const float* __restrict__ nf,
            const float* __restrict__ br1, const float* __restrict__ br2,
            const float* __restrict__ br3, const float* __restrict__ br4,
            float* __restrict__ out) {
    extern __shared__ char smemc[];
    __half* aH  = (__half*)(smemc + S_ACTH);
    __half* aL  = (__half*)(smemc + S_ACTL);
    float*  C32 = (float*)(smemc + S_C32);
    __half* Wb  = (__half*)(smemc + S_W);

    const int t = threadIdx.x, warp = t >> 5;
    const int n0 = blockIdx.x * 128;
    const int cnt = min(128, NN - n0);

    // gather Y = [nf | nf1 | nf2(fixed)] -> split act tiles, K = 128
    for (int idx = t; idx < 128 * 16; idx += NTHR) {
        int m = idx >> 4, g = idx & 15;
        int nd = n0 + min(m, cnt - 1);
        float v[8];
        if (g < 8)       ld8(v, nf + (size_t)nd * 64 + g * 8);
        else if (g < 12) ld8(v, g_nf1 + (size_t)nd * 32 + (g - 8) * 8);
        else {
            ld8(v, g_nf2 + (size_t)nd * 32 + (g - 12) * 8);
#pragma unroll
            for (int j = 0; j < 8; j++) if (!isfinite(v[j])) v[j] = 0.f;
        }
        store_split8(aH, aL, m, g * 8, v);
    }
    stageW(Wb, g_w + W_N1, 2 * S_N1, t);
    __syncthreads();

    mma_layer<128, 64>(aH, aL, Wb, Wb + S_N1, C32, warp);
    __syncthreads();
    epi<64, true>(C32, br1, aH, aL, t);
    stageW(Wb, g_w + W_N2, 2 * S_N2, t);
    __syncthreads();

    mma_layer<64, 128>(aH, aL, Wb, Wb + S_N2, C32, warp);
    __syncthreads();
    epi<128, true>(C32, br2, aH, aL, t);
    stageW(Wb, g_w + W_N3, 2 * S_N3, t);
    __syncthreads();

    mma_layer<128, 64>(aH, aL, Wb, Wb + S_N3, C32, warp);
    __syncthreads();
    epi<64, true>(C32, br3, aH, aL, t);
    stageW(Wb, g_w + W_N4, 2 * S_N4, t);
    __syncthreads();

    mma_layer<64, 64>(aH, aL, Wb, Wb + S_N4, C32, warp);
    __syncthreads();

    // final: bias + store f32
    for (int idx = t; idx < 128 * 64 / 4; idx += NTHR) {
        int m = idx >> 4, q = (idx & 15) * 4;
        if (m < cnt) {
            float4 v;
            v.x = C32[m * C_LD + q + 0] + br4[q + 0];
            v.y = C32[m * C_LD + q + 1] + br4[q + 1];
            v.z = C32[m * C_LD + q + 2] + br4[q + 2];
            v.w = C32[m * C_LD + q + 3] + br4[q + 3];
            *(float4*)(out + (size_t)(n0 + m) * 64 + q) = v;
        }
    }
}

// ---------------- launch ----------------
extern "C" void kernel_launch(void* const* d_in, const int* in_sizes, int n_in,
                              void* d_out, int out_size) {
    (void)in_sizes; (void)n_in; (void)out_size;
    const float* nf = (const float*)d_in[0];
    const float* ef = (const float*)d_in[1];
    const int* src  = (const int*)d_in[2];
    const int* dst  = (const int*)d_in[3];

    cudaFuncSetAttribute(edge_kernel, cudaFuncAttributeMaxDynamicSharedMemorySize, SMEM_B);
    cudaFuncSetAttribute(node_kernel, cudaFuncAttributeMaxDynamicSharedMemorySize, SMEM_B);

    prep_kernel<<<128, 256>>>(
        (const float*)d_in[4], (const float*)d_in[6],
        (const float*)d_in[8], (const float*)d_in[10],
        (const float*)d_in[12], (const float*)d_in[14],
        (const float*)d_in[16], (const float*)d_in[18]);
    init1_kernel<<<(NN * 32 + 255) / 256, 256>>>();
    init2_kernel<<<(NN * 32 + 255) / 256, 256>>>();

    edge_kernel<<<NE / 128, NTHR, SMEM_B>>>(
        nf, ef, src, dst,
        (const float*)d_in[5], (const float*)d_in[7],
        (const float*)d_in[9], (const float*)d_in[11]);

    node_kernel<<<(NN + 127) / 128, NTHR, SMEM_B>>>(
        nf,
        (const float*)d_in[13], (const float*)d_in[15],
        (const float*)d_in[17], (const float*)d_in[19],
        (float*)d_out);
}

// round 7
// speedup vs baseline: 1.7127x; 1.4354x over previous
#include <cuda_runtime.h>
#include <cuda_fp16.h>
#include <mma.h>
#include <math.h>
#include <stdint.h>

using namespace nvcuda;

#define NN 50000
#define NE 1600000
#define NTHR 256

// ---------------- device scratch ----------------
__device__ float g_nf1[NN * 32];
__device__ float g_nf2[NN * 32];

// fp16 split weight images, [N][K+8] row-major (padded stride for conflict-free
// ldmatrix), hi then lo contiguous per layer. offsets/sizes in halves.
#define W_E1 0
#define S_E1 9728    // 64 x (144+8)
#define W_E2 19456
#define S_E2 9216    // 128 x (64+8)
#define W_E3 37888
#define S_E3 8704    // 64 x (128+8)
#define W_E4 55296
#define S_E4 5760    // 80 x (64+8)  (col0 = gate, 1..64 feats, 65..79 zero)
#define W_N1 66816
#define S_N1 8704    // 64 x (128+8)
#define W_N2 84224
#define S_N2 9216    // 128 x (64+8)
#define W_N3 102656
#define S_N3 8704    // 64 x (128+8)
#define W_N4 120064
#define S_N4 4608    // 64 x (64+8)
#define W_TOT 129280
__device__ __align__(16) __half g_w[W_TOT];

// ---------------- smem layout (bytes) ----------------
#define ACT_LD 168               // halves; 336B stride -> conflict-free ldmatrix
#define C_LD   136               // floats
#define S_ACTH 0                 // 43008 = 128*168*2
#define S_ACTL 43008
#define S_C32  86016             // 69632 = 128*136*4
#define S_W    155648            // up to 38912 (2*S_E1)
#define S_SRC  194560            // 512
#define S_DST  195072            // 512
#define S_G    195584            // 512
#define SMEM_B 196096

__device__ __forceinline__ void atomicMaxF(float* a, float v) {
    if (v >= 0.f) atomicMax((int*)a, __float_as_int(v));
    else          atomicMin((unsigned int*)a, (unsigned int)__float_as_int(v));
}

__device__ __forceinline__ void split_h(float v, __half& hi, __half& lo) {
    hi = __float2half_rn(v);
    lo = __float2half_rn(v - __half2float(hi));
}

// write 8 consecutive split halves at act[m][k0..k0+7]
__device__ __forceinline__ void store_split8(__half* aH, __half* aL, int m, int k0,
                                             const float* v) {
    __half h[8], l[8];
#pragma unroll
    for (int j = 0; j < 8; j++) split_h(v[j], h[j], l[j]);
    *(uint4*)(aH + m * ACT_LD + k0) = *(const uint4*)h;
    *(uint4*)(aL + m * ACT_LD + k0) = *(const uint4*)l;
}

__device__ __forceinline__ void stageW(__half* dst, const __half* src, int halves, int t) {
    for (int i = t * 8; i < halves; i += NTHR * 8)
        *(uint4*)(dst + i) = *(const uint4*)(src + i);
}

__device__ __forceinline__ void ld8(float* v, const float* p) {
    float4 a = *(const float4*)p, b = *(const float4*)(p + 4);
    v[0] = a.x; v[1] = a.y; v[2] = a.z; v[3] = a.w;
    v[4] = b.x; v[5] = b.y; v[6] = b.z; v[7] = b.w;
}

// ---------------- wmma layer ----------------
// C[128][N] = act[128][K] x W[N][K]^T  (fp16 split x3, fp32 acc) -> C32 stage
// 8 warps: warp&3 -> 32-row m-group; warp>>2 -> n-tile parity (interleaved)
// Weights in smem [N][K+8] (LDW = K+8, conflict-free).
template<int K, int N>
__device__ __forceinline__ void mma_layer(const __half* actH, const __half* actL,
                                          const __half* WH, const __half* WL,
                                          float* C32, int warp) {
    constexpr int NT = N / 16;
    constexpr int MX = (NT + 1) / 2;
    constexpr int LDW = K + 8;
    const int m0 = (warp & 3) * 32;
    const int nh = warp >> 2;

    wmma::fragment<wmma::accumulator, 16, 16, 16, float> acc[2][MX];
#pragma unroll
    for (int i = 0; i < MX; i++)
        if (nh + 2 * i < NT) {
            wmma::fill_fragment(acc[0][i], 0.f);
            wmma::fill_fragment(acc[1][i], 0.f);
        }

#pragma unroll 1
    for (int k0 = 0; k0 < K; k0 += 16) {
        wmma::fragment<wmma::matrix_a, 16, 16, 16, __half, wmma::row_major> aH0, aH1, aL0, aL1;
        wmma::load_matrix_sync(aH0, actH + m0 * ACT_LD + k0, ACT_LD);
        wmma::load_matrix_sync(aH1, actH + (m0 + 16) * ACT_LD + k0, ACT_LD);
        wmma::load_matrix_sync(aL0, actL + m0 * ACT_LD + k0, ACT_LD);
        wmma::load_matrix_sync(aL1, actL + (m0 + 16) * ACT_LD + k0, ACT_LD);
#pragma unroll
        for (int i = 0; i < MX; i++) {
            const int nt = nh + 2 * i;
            if (nt < NT) {
                wmma::fragment<wmma::matrix_b, 16, 16, 16, __half, wmma::col_major> bH, bL;
                wmma::load_matrix_sync(bH, WH + nt * 16 * LDW + k0, LDW);
                wmma::load_matrix_sync(bL, WL + nt * 16 * LDW + k0, LDW);
                wmma::mma_sync(acc[0][i], aH0, bH, acc[0][i]);
                wmma::mma_sync(acc[1][i], aH1, bH, acc[1][i]);
                wmma::mma_sync(acc[0][i], aH0, bL, acc[0][i]);
                wmma::mma_sync(acc[1][i], aH1, bL, acc[1][i]);
                wmma::mma_sync(acc[0][i], aL0, bH, acc[0][i]);
                wmma::mma_sync(acc[1][i], aL1, bH, acc[1][i]);
            }
        }
    }
#pragma unroll
    for (int i = 0; i < MX; i++) {
        const int nt = nh + 2 * i;
        if (nt < NT) {
            wmma::store_matrix_sync(C32 + m0 * C_LD + nt * 16, acc[0][i], C_LD,
                                    wmma::mem_row_major);
            wmma::store_matrix_sync(C32 + (m0 + 16) * C_LD + nt * 16, acc[1][i], C_LD,
                                    wmma::mem_row_major);
        }
    }
}

// bias + leaky relu + split -> act buffers
template<int N, bool RELU>
__device__ __forceinline__ void epi(const float* C32, const float* __restrict__ bias,
                                    __half* aH, __half* aL, int t) {
    for (int idx = t; idx < 128 * N / 8; idx += NTHR) {
        int m = idx / (N / 8), q = idx - m * (N / 8);
        int n = q * 8;
        float v[8];
#pragma unroll
        for (int j = 0; j < 8; j++) {
            float x = C32[m * C_LD + n + j] + bias[n + j];
            if (RELU) x = fmaxf(x, 0.2f * x);
            v[j] = x;
        }
        store_split8(aH, aL, m, n, v);
    }
}

// ---------------- prep / init ----------------
// Kp = padded row stride (Kmma + 8), Kmma = K used by MMA, Kr/Nr = real dims
__device__ __forceinline__ void fill_img(int tid, int stride, int base, int S,
                                         const float* __restrict__ W,
                                         int Kr, int Nr, int Kp, int Np) {
    for (int i = tid; i < Np * Kp; i += stride) {
        int n = i / Kp, k = i - n * Kp;
        float v = (k < Kr && n < Nr) ? W[k * Nr + n] : 0.f;
        __half hi, lo;
        split_h(v, hi, lo);
        g_w[base + i] = hi;
        g_w[base + S + i] = lo;
    }
}

extern "C" __global__ void prep_kernel(const float* Wm1, const float* Wm2,
                                       const float* Wm3, const float* Wm4,
                                       const float* Wr1, const float* Wr2,
                                       const float* Wr3, const float* Wr4) {
    int tid = blockIdx.x * blockDim.x + threadIdx.x;
    int stride = gridDim.x * blockDim.x;
    fill_img(tid, stride, W_E1, S_E1, Wm1, 144, 64, 152, 64);
    fill_img(tid, stride, W_E2, S_E2, Wm2, 64, 128, 72, 128);
    fill_img(tid, stride, W_E3, S_E3, Wm3, 128, 64, 136, 64);
    fill_img(tid, stride, W_E4, S_E4, Wm4, 64, 65, 72, 80);
    fill_img(tid, stride, W_N1, S_N1, Wr1, 128, 64, 136, 64);
    fill_img(tid, stride, W_N2, S_N2, Wr2, 64, 128, 72, 128);
    fill_img(tid, stride, W_N3, S_N3, Wr3, 128, 64, 136, 64);
    fill_img(tid, stride, W_N4, S_N4, Wr4, 64, 64, 72, 64);
}

extern "C" __global__ void init1_kernel() {
    int i = blockIdx.x * blockDim.x + threadIdx.x;
    if (i < NN * 32) g_nf1[i] = 0.f;
}
extern "C" __global__ void init2_kernel() {
    int i = blockIdx.x * blockDim.x + threadIdx.x;
    if (i < NN * 32) g_nf2[i] = -INFINITY;
}

// ---------------- edge kernel ----------------
extern "C" __global__ void __launch_bounds__(NTHR)
edge_kernel(const float* __restrict__ nf, const float* __restrict__ ef,
            const int* __restrict__ src, const int* __restrict__ dst,
            const float* __restrict__ bm1, const float* __restrict__ bm2,
            const float* __restrict__ bm3, const float* __restrict__ bm4) {
    extern __shared__ char smemc[];
    __half* aH  = (__half*)(smemc + S_ACTH);
    __half* aL  = (__half*)(smemc + S_ACTL);
    float*  C32 = (float*)(smemc + S_C32);
    __half* Wb  = (__half*)(smemc + S_W);
    int* ssrc = (int*)(smemc + S_SRC);
    int* sdst = (int*)(smemc + S_DST);
    float* sg = (float*)(smemc + S_G);

    const int t = threadIdx.x, warp = t >> 5;
    const int e0 = blockIdx.x * 128;

    if (t < 128) { ssrc[t] = src[e0 + t]; sdst[t] = dst[e0 + t]; }
    __syncthreads();

    // gather X = [nf[src] | nf[dst] | ef] -> split act tiles, K = 144
    for (int idx = t; idx < 128 * 18; idx += NTHR) {
        int m = idx / 18, g = idx - m * 18;
        float v[8];
        if (g < 8)       ld8(v, nf + (size_t)ssrc[m] * 64 + g * 8);
        else if (g < 16) ld8(v, nf + (size_t)sdst[m] * 64 + (g - 8) * 8);
        else             ld8(v, ef + (size_t)(e0 + m) * 16 + (g - 16) * 8);
        store_split8(aH, aL, m, g * 8, v);
    }
    stageW(Wb, g_w + W_E1, 2 * S_E1, t);
    __syncthreads();

    mma_layer<144, 64>(aH, aL, Wb, Wb + S_E1, C32, warp);
    __syncthreads();
    epi<64, true>(C32, bm1, aH, aL, t);
    stageW(Wb, g_w + W_E2, 2 * S_E2, t);
    __syncthreads();

    mma_layer<64, 128>(aH, aL, Wb, Wb + S_E2, C32, warp);
    __syncthreads();
    epi<128, true>(C32, bm2, aH, aL, t);
    stageW(Wb, g_w + W_E3, 2 * S_E3, t);
    __syncthreads();

    mma_layer<128, 64>(aH, aL, Wb, Wb + S_E3, C32, warp);
    __syncthreads();
    epi<64, true>(C32, bm3, aH, aL, t);
    stageW(Wb, g_w + W_E4, 2 * S_E4, t);
    __syncthreads();

    mma_layer<64, 80>(aH, aL, Wb, Wb + S_E4, C32, warp);
    __syncthreads();

    // gate
    if (t < 128) sg[t] = 1.f / (1.f + expf(-(C32[t * C_LD] + bm4[0])));
    __syncthreads();

    // scatter: feats 0..31 -> sum, 32..63 -> max (C32 cols 1..64)
    for (int idx = t; idx < 8192; idx += NTHR) {
        int h = idx >> 7, m = idx & 127;
        float val = (C32[m * C_LD + 1 + h] + bm4[1 + h]) * sg[m];
        int d = sdst[m];
        if (h < 32) atomicAdd(&g_nf1[d * 32 + h], val);
        else        atomicMaxF(&g_nf2[d * 32 + (h - 32)], val);
    }
}

// ---------------- node kernel ----------------
extern "C" __global__ void __launch_bounds__(NTHR)
node_kernel(const float* __restrict__ nf,
            const float* __restrict__ br1, const float* __restrict__ br2,
            const float* __restrict__ br3, const float* __restrict__ br4,
            float* __restrict__ out) {
    extern __shared__ char smemc[];
    __half* aH  = (__half*)(smemc + S_ACTH);
    __half* aL  = (__half*)(smemc + S_ACTL);
    float*  C32 = (float*)(smemc + S_C32);
    __half* Wb  = (__half*)(smemc + S_W);

    const int t = threadIdx.x, warp = t >> 5;
    const int n0 = blockIdx.x * 128;
    const int cnt = min(128, NN - n0);

    // gather Y = [nf | nf1 | nf2(fixed)] -> split act tiles, K = 128
    for (int idx = t; idx < 128 * 16; idx += NTHR) {
        int m = idx >> 4, g = idx & 15;
        int nd = n0 + min(m, cnt - 1);
        float v[8];
        if (g < 8)       ld8(v, nf + (size_t)nd * 64 + g * 8);
        else if (g < 12) ld8(v, g_nf1 + (size_t)nd * 32 + (g - 8) * 8);
        else {
            ld8(v, g_nf2 + (size_t)nd * 32 + (g - 12) * 8);
#pragma unroll
            for (int j = 0; j < 8; j++) if (!isfinite(v[j])) v[j] = 0.f;
        }
        store_split8(aH, aL, m, g * 8, v);
    }
    stageW(Wb, g_w + W_N1, 2 * S_N1, t);
    __syncthreads();

    mma_layer<128, 64>(aH, aL, Wb, Wb + S_N1, C32, warp);
    __syncthreads();
    epi<64, true>(C32, br1, aH, aL, t);
    stageW(Wb, g_w + W_N2, 2 * S_N2, t);
    __syncthreads();

    mma_layer<64, 128>(aH, aL, Wb, Wb + S_N2, C32, warp);
    __syncthreads();
    epi<128, true>(C32, br2, aH, aL, t);
    stageW(Wb, g_w + W_N3, 2 * S_N3, t);
    __syncthreads();

    mma_layer<128, 64>(aH, aL, Wb, Wb + S_N3, C32, warp);
    __syncthreads();
    epi<64, true>(C32, br3, aH, aL, t);
    stageW(Wb, g_w + W_N4, 2 * S_N4, t);
    __syncthreads();

    mma_layer<64, 64>(aH, aL, Wb, Wb + S_N4, C32, warp);
    __syncthreads();

    // final: bias + store f32
    for (int idx = t; idx < 128 * 64 / 4; idx += NTHR) {
        int m = idx >> 4, q = (idx & 15) * 4;
        if (m < cnt) {
            float4 v;
            v.x = C32[m * C_LD + q + 0] + br4[q + 0];
            v.y = C32[m * C_LD + q + 1] + br4[q + 1];
            v.z = C32[m * C_LD + q + 2] + br4[q + 2];
            v.w = C32[m * C_LD + q + 3] + br4[q + 3];
            *(float4*)(out + (size_t)(n0 + m) * 64 + q) = v;
        }
    }
}

// ---------------- launch ----------------
extern "C" void kernel_launch(void* const* d_in, const int* in_sizes, int n_in,
                              void* d_out, int out_size) {
    (void)in_sizes; (void)n_in; (void)out_size;
    const float* nf = (const float*)d_in[0];
    const float* ef = (const float*)d_in[1];
    const int* src  = (const int*)d_in[2];
    const int* dst  = (const int*)d_in[3];

    cudaFuncSetAttribute(edge_kernel, cudaFuncAttributeMaxDynamicSharedMemorySize, SMEM_B);
    cudaFuncSetAttribute(node_kernel, cudaFuncAttributeMaxDynamicSharedMemorySize, SMEM_B);

    prep_kernel<<<128, 256>>>(
        (const float*)d_in[4], (const float*)d_in[6],
        (const float*)d_in[8], (const float*)d_in[10],
        (const float*)d_in[12], (const float*)d_in[14],
        (const float*)d_in[16], (const float*)d_in[18]);
    init1_kernel<<<(NN * 32 + 255) / 256, 256>>>();
    init2_kernel<<<(NN * 32 + 255) / 256, 256>>>();

    edge_kernel<<<NE / 128, NTHR, SMEM_B>>>(
        nf, ef, src, dst,
        (const float*)d_in[5], (const float*)d_in[7],
        (const float*)d_in[9], (const float*)d_in[11]);

    node_kernel<<<(NN + 127) / 128, NTHR, SMEM_B>>>(
        nf,
        (const float*)d_in[13], (const float*)d_in[15],
        (const float*)d_in[17], (const float*)d_in[19],
        (float*)d_out);
}

// round 11
// speedup vs baseline: 2.9715x; 1.7350x over previous
#include <cuda_runtime.h>
#include <cuda_fp16.h>
#include <math.h>
#include <stdint.h>

#define NN 50000
#define NE 1600000
#define NTHR 256

// ---------------- device scratch ----------------
__device__ float g_nf1[NN * 32];
__device__ float g_nf2[NN * 32];

// Weight images per layer: [hi padded: Np x (Kr+8) halves, ldmatrix-friendly]
// then [lo unpadded: Np x Kr halves, XOR-swizzled for LDS.32].
#define WO_E1 0
#define WO_E2 37888
#define WO_E3 72704
#define WO_E4 106496
#define WO_N1 128256
#define WO_N2 162048
#define WO_N3 196864
#define WO_N4 230656
#define W_IMG_TOTAL 248064
__device__ __align__(16) unsigned char g_wimg[W_IMG_TOTAL];

#define WH_E1 19456
#define WH_E2 18432
#define WH_E3 17408
#define WH_E4 11520
#define WH_N1 17408
#define WH_N2 18432
#define WH_N3 17408
#define WH_N4 9216
#define WT_E1 37888
#define WT_E2 34816
#define WT_E3 33792
#define WT_E4 21760
#define WT_N1 33792
#define WT_N2 34816
#define WT_N3 33792
#define WT_N4 17408

// ---------------- smem layout (bytes) ----------------
#define LDH 152                  // act-hi halves/row (304B, conflict-free ldmatrix)
#define ALB 288                  // act-lo row bytes (144 halves, swizzled)
#define SM_AH 0                  // 38912
#define SM_AL 38912              // 36864
#define SM_W  75776              // 37888 max
#define SM_DST 113664            // 512
#define SM_SG  114176            // 512
#define SMEM_TOT 114688

// XOR swizzle: 16B chunks within a row; chunks >=16 left unswizzled.
__device__ __forceinline__ int swz(int row, int halfIdx, int rowBytes) {
    int b = halfIdx * 2;
    int chunk = b >> 4, w = b & 15;
    if (chunk < 16) chunk ^= (row & 7);
    return row * rowBytes + (chunk << 4) + w;
}

// ---------------- asm helpers ----------------
__device__ __forceinline__ uint32_t smem_u32(const void* p) {
    uint32_t a;
    asm("{ .reg .u64 t; cvta.to.shared.u64 t, %1; cvt.u32.u64 %0, t; }" : "=r"(a) : "l"(p));
    return a;
}
__device__ __forceinline__ void ldsm4(uint32_t* r, uint32_t addr) {
    asm volatile("ldmatrix.sync.aligned.m8n8.x4.shared.b16 {%0,%1,%2,%3}, [%4];"
                 : "=r"(r[0]), "=r"(r[1]), "=r"(r[2]), "=r"(r[3]) : "r"(addr));
}
__device__ __forceinline__ void ldsm2(uint32_t* r, uint32_t addr) {
    asm volatile("ldmatrix.sync.aligned.m8n8.x2.shared.b16 {%0,%1}, [%2];"
                 : "=r"(r[0]), "=r"(r[1]) : "r"(addr));
}
__device__ __forceinline__ void mma16816(float* d, const uint32_t* a, const uint32_t* b) {
    asm volatile(
        "mma.sync.aligned.m16n8k16.row.col.f32.f16.f16.f32 "
        "{%0,%1,%2,%3}, {%4,%5,%6,%7}, {%8,%9}, {%0,%1,%2,%3};"
        : "+f"(d[0]), "+f"(d[1]), "+f"(d[2]), "+f"(d[3])
        : "r"(a[0]), "r"(a[1]), "r"(a[2]), "r"(a[3]), "r"(b[0]), "r"(b[1]));
}

// ---------------- misc ----------------
__device__ __forceinline__ void atomicMaxF(float* a, float v) {
    if (v >= 0.f) atomicMax((int*)a, __float_as_int(v));
    else          atomicMin((unsigned int*)a, (unsigned int)__float_as_int(v));
}
__device__ __forceinline__ void split2(float a, float b, uint32_t& hi, uint32_t& lo) {
    __half ha = __float2half_rn(a), hb = __float2half_rn(b);
    __half la = __float2half_rn(a - __half2float(ha));
    __half lb = __float2half_rn(b - __half2float(hb));
    hi = (uint32_t)__half_as_ushort(ha) | ((uint32_t)__half_as_ushort(hb) << 16);
    lo = (uint32_t)__half_as_ushort(la) | ((uint32_t)__half_as_ushort(lb) << 16);
}
__device__ __forceinline__ void store_split8(char* smc, int m, int k0, const float* v) {
    uint32_t h[4], l[4];
    split2(v[0], v[1], h[0], l[0]);
    split2(v[2], v[3], h[1], l[1]);
    split2(v[4], v[5], h[2], l[2]);
    split2(v[6], v[7], h[3], l[3]);
    *(uint4*)(smc + SM_AH + (m * LDH + k0) * 2) = make_uint4(h[0], h[1], h[2], h[3]);
    *(uint4*)(smc + SM_AL + swz(m, k0, ALB)) = make_uint4(l[0], l[1], l[2], l[3]);
}
__device__ __forceinline__ void stageW(char* dst, const unsigned char* src, int bytes, int t) {
    for (int i = t * 16; i < bytes; i += NTHR * 16)
        *(uint4*)(dst + i) = *(const uint4*)(src + i);
}
__device__ __forceinline__ void ld8(float* v, const float* p) {
    float4 a = *(const float4*)p, b = *(const float4*)(p + 4);
    v[0] = a.x; v[1] = a.y; v[2] = a.z; v[3] = a.w;
    v[4] = b.x; v[5] = b.y; v[6] = b.z; v[7] = b.w;
}

// ---------------- core GEMM: acc += (Ah+Al)x(Wh+Wl), 3-term split ----------------
template<int K, int NW>
__device__ __forceinline__ void mma_compute(float (&acc)[NW / 8][2][4],
                                            const char* smc, uint32_t SB,
                                            int wLoff, int warp, int lane) {
    constexpr int NT = NW / 8;
    constexpr int WLDH = K + 8;
    constexpr int WLB = K * 2;
    const int m0 = (warp & 3) * 32;
    const int n0 = (warp >> 2) * NW;
    const int arow = m0 + (lane & 7) + ((lane >> 3) & 1) * 8;
    const int acol8 = (lane >> 4) * 8;
    const int brow = lane & 7;
    const int bk8 = ((lane >> 3) & 1) * 8;
    const int rq = lane >> 2, cq = 2 * (lane & 3);
    const uint32_t aHb = SB + SM_AH;
    const uint32_t wHb = SB + SM_W;
    const char* aLp = smc + SM_AL;
    const char* wLp = smc + SM_W + wLoff;

#pragma unroll 1
    for (int k0 = 0; k0 < K; k0 += 16) {
        uint32_t ah[2][4], al[2][4];
#pragma unroll
        for (int mt = 0; mt < 2; mt++) {
            ldsm4(ah[mt], aHb + (uint32_t)((arow + mt * 16) * LDH + k0 + acol8) * 2);
            int r0 = m0 + mt * 16 + rq;
            int kk = k0 + cq;
            al[mt][0] = *(const uint32_t*)(aLp + swz(r0, kk, ALB));
            al[mt][1] = *(const uint32_t*)(aLp + swz(r0 + 8, kk, ALB));
            al[mt][2] = *(const uint32_t*)(aLp + swz(r0, kk + 8, ALB));
            al[mt][3] = *(const uint32_t*)(aLp + swz(r0 + 8, kk + 8, ALB));
        }
#pragma unroll
        for (int nt = 0; nt < NT; nt++) {
            uint32_t bh[2], bl[2];
            ldsm2(bh, wHb + (uint32_t)((n0 + nt * 8 + brow) * WLDH + k0 + bk8) * 2);
            int bn = n0 + nt * 8 + rq;
            bl[0] = *(const uint32_t*)(wLp + swz(bn, k0 + cq, WLB));
            bl[1] = *(const uint32_t*)(wLp + swz(bn, k0 + cq + 8, WLB));
#pragma unroll
            for (int mt = 0; mt < 2; mt++) {
                mma16816(acc[nt][mt], ah[mt], bh);
                mma16816(acc[nt][mt], ah[mt], bl);
                mma16816(acc[nt][mt], al[mt], bh);
            }
        }
    }
}

template<int NW, int NREAL>
__device__ __forceinline__ void init_bias(float (&acc)[NW / 8][2][4],
                                          const float* __restrict__ bias, int warp, int lane) {
    const int n0 = (warp >> 2) * NW;
    const int cq = 2 * (lane & 3);
#pragma unroll
    for (int nt = 0; nt < NW / 8; nt++) {
        int c = n0 + nt * 8 + cq;
        float b0 = (c < NREAL) ? bias[c] : 0.f;
        float b1 = (c + 1 < NREAL) ? bias[c + 1] : 0.f;
#pragma unroll
        for (int mt = 0; mt < 2; mt++) {
            acc[nt][mt][0] = b0; acc[nt][mt][1] = b1;
            acc[nt][mt][2] = b0; acc[nt][mt][3] = b1;
        }
    }
}

// register epilogue: leaky-relu + split + store to act tiles.
// MUST be preceded by __syncthreads() (act rows are read by other warps' MMAs).
template<int NW, bool RELU>
__device__ __forceinline__ void epi_split(float (&acc)[NW / 8][2][4],
                                          char* smc, int warp, int lane) {
    const int m0 = (warp & 3) * 32;
    const int n0 = (warp >> 2) * NW;
    const int rq = lane >> 2, cq = 2 * (lane & 3);
#pragma unroll
    for (int nt = 0; nt < NW / 8; nt++) {
#pragma unroll
        for (int mt = 0; mt < 2; mt++) {
            int r = m0 + mt * 16 + rq;
            int c = n0 + nt * 8 + cq;
            float v0 = acc[nt][mt][0], v1 = acc[nt][mt][1];
            float v2 = acc[nt][mt][2], v3 = acc[nt][mt][3];
            if (RELU) {
                v0 = fmaxf(v0, 0.2f * v0); v1 = fmaxf(v1, 0.2f * v1);
                v2 = fmaxf(v2, 0.2f * v2); v3 = fmaxf(v3, 0.2f * v3);
            }
            uint32_t h01, l01, h23, l23;
            split2(v0, v1, h01, l01);
            split2(v2, v3, h23, l23);
            *(uint32_t*)(smc + SM_AH + (r * LDH + c) * 2) = h01;
            *(uint32_t*)(smc + SM_AH + ((r + 8) * LDH + c) * 2) = h23;
            *(uint32_t*)(smc + SM_AL + swz(r, c, ALB)) = l01;
            *(uint32_t*)(smc + SM_AL + swz(r + 8, c, ALB)) = l23;
        }
    }
}

// ---------------- prep / init ----------------
__device__ void fill_layer(int tid, int stride, int baseB, const float* __restrict__ W,
                           int Kr, int Nr, int Np) {
    int Kp = Kr + 8;
    for (int i = tid; i < Np * Kp; i += stride) {
        int n = i / Kp, k = i - n * Kp;
        float v = (k < Kr && n < Nr) ? W[k * Nr + n] : 0.f;
        *(__half*)(g_wimg + baseB + i * 2) = __float2half_rn(v);
    }
    int loB = baseB + Np * Kp * 2;
    for (int i = tid; i < Np * Kr; i += stride) {
        int n = i / Kr, k = i - n * Kr;
        float v = (n < Nr) ? W[k * Nr + n] : 0.f;
        __half h = __float2half_rn(v);
        __half l = __float2half_rn(v - __half2float(h));
        *(__half*)(g_wimg + loB + swz(n, k, Kr * 2)) = l;
    }
}

extern "C" __global__ void prep_kernel(const float* Wm1, const float* Wm2,
                                       const float* Wm3, const float* Wm4,
                                       const float* Wr1, const float* Wr2,
                                       const float* Wr3, const float* Wr4) {
    int tid = blockIdx.x * blockDim.x + threadIdx.x;
    int stride = gridDim.x * blockDim.x;
    fill_layer(tid, stride, WO_E1, Wm1, 144, 64, 64);
    fill_layer(tid, stride, WO_E2, Wm2, 64, 128, 128);
    fill_layer(tid, stride, WO_E3, Wm3, 128, 64, 64);
    fill_layer(tid, stride, WO_E4, Wm4, 64, 65, 80);
    fill_layer(tid, stride, WO_N1, Wr1, 128, 64, 64);
    fill_layer(tid, stride, WO_N2, Wr2, 64, 128, 128);
    fill_layer(tid, stride, WO_N3, Wr3, 128, 64, 64);
    fill_layer(tid, stride, WO_N4, Wr4, 64, 64, 64);
}

extern "C" __global__ void init1_kernel() {
    int i = blockIdx.x * blockDim.x + threadIdx.x;
    if (i < NN * 32) g_nf1[i] = 0.f;
}
extern "C" __global__ void init2_kernel() {
    int i = blockIdx.x * blockDim.x + threadIdx.x;
    if (i < NN * 32) g_nf2[i] = -INFINITY;
}

// ---------------- edge kernel ----------------
extern "C" __global__ void __launch_bounds__(NTHR, 2)
edge_kernel(const float* __restrict__ nf, const float* __restrict__ ef,
            const int* __restrict__ src, const int* __restrict__ dst,
            const float* __restrict__ bm1, const float* __restrict__ bm2,
            const float* __restrict__ bm3, const float* __restrict__ bm4) {
    extern __shared__ char smc[];
    const uint32_t SB = smem_u32(smc);
    int* sdst = (int*)(smc + SM_DST);
    float* sg = (float*)(smc + SM_SG);
    const int t = threadIdx.x, warp = t >> 5, lane = t & 31;
    const int e0 = blockIdx.x * 128;

    if (t < 128) sdst[t] = dst[e0 + t];

    // gather X = [nf[src] | nf[dst] | ef] -> split act tiles (K=144)
    for (int idx = t; idx < 128 * 18; idx += NTHR) {
        int m = idx / 18, g = idx - m * 18;
        float v[8];
        if (g < 8)       ld8(v, nf + (size_t)src[e0 + m] * 64 + g * 8);
        else if (g < 16) ld8(v, nf + (size_t)dst[e0 + m] * 64 + (g - 8) * 8);
        else             ld8(v, ef + (size_t)(e0 + m) * 16 + (g - 16) * 8);
        store_split8(smc, m, g * 8, v);
    }
    stageW(smc + SM_W, g_wimg + WO_E1, WT_E1, t);
    __syncthreads();

    { // L1: 144 -> 64
        float acc[4][2][4];
        init_bias<32, 64>(acc, bm1, warp, lane);
        mma_compute<144, 32>(acc, smc, SB, WH_E1, warp, lane);
        __syncthreads();                    // all reads of act done before overwrite
        epi_split<32, true>(acc, smc, warp, lane);
    }
    __syncthreads();
    stageW(smc + SM_W, g_wimg + WO_E2, WT_E2, t);
    __syncthreads();

    { // L2: 64 -> 128
        float acc[8][2][4];
        init_bias<64, 128>(acc, bm2, warp, lane);
        mma_compute<64, 64>(acc, smc, SB, WH_E2, warp, lane);
        __syncthreads();
        epi_split<64, true>(acc, smc, warp, lane);
    }
    __syncthreads();
    stageW(smc + SM_W, g_wimg + WO_E3, WT_E3, t);
    __syncthreads();

    { // L3: 128 -> 64
        float acc[4][2][4];
        init_bias<32, 64>(acc, bm3, warp, lane);
        mma_compute<128, 32>(acc, smc, SB, WH_E3, warp, lane);
        __syncthreads();
        epi_split<32, true>(acc, smc, warp, lane);
    }
    __syncthreads();
    stageW(smc + SM_W, g_wimg + WO_E4, WT_E4, t);
    __syncthreads();

    { // L4: 64 -> 80 (col0 gate, 1..64 feats, 65..79 pad)
        float acc[5][2][4];
        init_bias<40, 65>(acc, bm4, warp, lane);
        mma_compute<64, 40>(acc, smc, SB, WH_E4, warp, lane);

        const int m0 = (warp & 3) * 32;
        const int n0 = (warp >> 2) * 40;
        const int rq = lane >> 2, cq = 2 * (lane & 3);
        if ((warp >> 2) == 0 && (lane & 3) == 0) {
#pragma unroll
            for (int mt = 0; mt < 2; mt++) {
                int r = m0 + mt * 16 + rq;
                sg[r] = 1.f / (1.f + expf(-acc[0][mt][0]));
                sg[r + 8] = 1.f / (1.f + expf(-acc[0][mt][2]));
            }
        }
        __syncthreads();
#pragma unroll
        for (int nt = 0; nt < 5; nt++) {
#pragma unroll
            for (int mt = 0; mt < 2; mt++) {
#pragma unroll
                for (int e = 0; e < 4; e++) {
                    int col = n0 + nt * 8 + cq + (e & 1);
                    int row = m0 + mt * 16 + rq + (e >> 1) * 8;
                    if (col >= 1 && col <= 64) {
                        float val = acc[nt][mt][e] * sg[row];
                        int d = sdst[row];
                        int h = col - 1;
                        if (h < 32) atomicAdd(&g_nf1[d * 32 + h], val);
                        else        atomicMaxF(&g_nf2[d * 32 + h - 32], val);
                    }
                }
            }
        }
    }
}

// ---------------- node kernel ----------------
extern "C" __global__ void __launch_bounds__(NTHR, 2)
node_kernel(const float* __restrict__ nf,
            const float* __restrict__ br1, const float* __restrict__ br2,
            const float* __restrict__ br3, const float* __restrict__ br4,
            float* __restrict__ out) {
    extern __shared__ char smc[];
    const uint32_t SB = smem_u32(smc);
    const int t = threadIdx.x, warp = t >> 5, lane = t & 31;
    const int n0g = blockIdx.x * 128;
    const int cnt = min(128, NN - n0g);

    // gather Y = [nf | nf1 | nf2(fixed)] -> split act tiles (K=128)
    for (int idx = t; idx < 128 * 16; idx += NTHR) {
        int m = idx >> 4, g = idx & 15;
        int nd = n0g + min(m, cnt - 1);
        float v[8];
        if (g < 8)       ld8(v, nf + (size_t)nd * 64 + g * 8);
        else if (g < 12) ld8(v, g_nf1 + (size_t)nd * 32 + (g - 8) * 8);
        else {
            ld8(v, g_nf2 + (size_t)nd * 32 + (g - 12) * 8);
#pragma unroll
            for (int j = 0; j < 8; j++) if (!isfinite(v[j])) v[j] = 0.f;
        }
        store_split8(smc, m, g * 8, v);
    }
    stageW(smc + SM_W, g_wimg + WO_N1, WT_N1, t);
    __syncthreads();

    { float acc[4][2][4];
      init_bias<32, 64>(acc, br1, warp, lane);
      mma_compute<128, 32>(acc, smc, SB, WH_N1, warp, lane);
      __syncthreads();
      epi_split<32, true>(acc, smc, warp, lane); }
    __syncthreads();
    stageW(smc + SM_W, g_wimg + WO_N2, WT_N2, t);
    __syncthreads();

    { float acc[8][2][4];
      init_bias<64, 128>(acc, br2, warp, lane);
      mma_compute<64, 64>(acc, smc, SB, WH_N2, warp, lane);
      __syncthreads();
      epi_split<64, true>(acc, smc, warp, lane); }
    __syncthreads();
    stageW(smc + SM_W, g_wimg + WO_N3, WT_N3, t);
    __syncthreads();

    { float acc[4][2][4];
      init_bias<32, 64>(acc, br3, warp, lane);
      mma_compute<128, 32>(acc, smc, SB, WH_N3, warp, lane);
      __syncthreads();
      epi_split<32, true>(acc, smc, warp, lane); }
    __syncthreads();
    stageW(smc + SM_W, g_wimg + WO_N4, WT_N4, t);
    __syncthreads();

    { // final: 64 -> 64, store f32 to out (no act write -> no extra sync needed)
        float acc[4][2][4];
        init_bias<32, 64>(acc, br4, warp, lane);
        mma_compute<64, 32>(acc, smc, SB, WH_N4, warp, lane);
        const int m0 = (warp & 3) * 32;
        const int n0 = (warp >> 2) * 32;
        const int rq = lane >> 2, cq = 2 * (lane & 3);
#pragma unroll
        for (int nt = 0; nt < 4; nt++) {
#pragma unroll
            for (int mt = 0; mt < 2; mt++) {
#pragma unroll
                for (int e = 0; e < 4; e++) {
                    int col = n0 + nt * 8 + cq + (e & 1);
                    int row = m0 + mt * 16 + rq + (e >> 1) * 8;
                    if (row < cnt)
                        out[(size_t)(n0g + row) * 64 + col] = acc[nt][mt][e];
                }
            }
        }
    }
}

// ---------------- launch ----------------
extern "C" void kernel_launch(void* const* d_in, const int* in_sizes, int n_in,
                              void* d_out, int out_size) {
    (void)in_sizes; (void)n_in; (void)out_size;
    const float* nf = (const float*)d_in[0];
    const float* ef = (const float*)d_in[1];
    const int* src  = (const int*)d_in[2];
    const int* dst  = (const int*)d_in[3];

    cudaFuncSetAttribute(edge_kernel, cudaFuncAttributeMaxDynamicSharedMemorySize, SMEM_TOT);
    cudaFuncSetAttribute(node_kernel, cudaFuncAttributeMaxDynamicSharedMemorySize, SMEM_TOT);

    prep_kernel<<<128, 256>>>(
        (const float*)d_in[4], (const float*)d_in[6],
        (const float*)d_in[8], (const float*)d_in[10],
        (const float*)d_in[12], (const float*)d_in[14],
        (const float*)d_in[16], (const float*)d_in[18]);
    init1_kernel<<<(NN * 32 + 255) / 256, 256>>>();
    init2_kernel<<<(NN * 32 + 255) / 256, 256>>>();

    edge_kernel<<<NE / 128, NTHR, SMEM_TOT>>>(
        nf, ef, src, dst,
        (const float*)d_in[5], (const float*)d_in[7],
        (const float*)d_in[9], (const float*)d_in[11]);

    node_kernel<<<(NN + 127) / 128, NTHR, SMEM_TOT>>>(
        nf,
        (const float*)d_in[13], (const float*)d_in[15],
        (const float*)d_in[17], (const float*)d_in[19],
        (float*)d_out);
}

// round 13
// speedup vs baseline: 3.0737x; 1.0344x over previous
#include <cuda_runtime.h>
#include <cuda_fp16.h>
#include <math.h>
#include <stdint.h>

#define NN 50000
#define NE 1600000
#define NTHR 256

// ---------------- device scratch ----------------
__device__ float g_nf1[NN * 32];
__device__ float g_nf2[NN * 32];
__device__ __align__(16) __half g_nfh[NN * 64];   // nf fp16 hi
__device__ __align__(16) __half g_nfl[NN * 64];   // nf fp16 lo

// Weight images per layer: [hi padded: Np x (Kr+8) halves, ldmatrix-friendly]
// then [lo: Np rows, paired-u64 layout, stride 136B (K=64) / 288B (K=128/144)].
#define WO_E1 0
#define WO_E2 37888
#define WO_E3 73728
#define WO_E4 109568
#define WO_N1 131968
#define WO_N2 167808
#define WO_N3 203648
#define WO_N4 239488
#define W_IMG_TOTAL 257408
__device__ __align__(16) unsigned char g_wimg[W_IMG_TOTAL];

#define WH_E1 19456
#define WH_E2 18432
#define WH_E3 17408
#define WH_E4 11520
#define WH_N1 17408
#define WH_N2 18432
#define WH_N3 17408
#define WH_N4 9216
#define WT_E1 37888
#define WT_E2 35840
#define WT_E3 35840
#define WT_E4 22400
#define WT_N1 35840
#define WT_N2 35840
#define WT_N3 35840
#define WT_N4 17920

// ---------------- smem layout (bytes) ----------------
#define LDH 152                  // act-hi halves/row (304B, conflict-free ldmatrix)
#define ALB 288                  // act-lo row bytes, paired-u64 layout (36 u64 = 4 mod 16)
#define SM_AH 0                  // 38912
#define SM_AL 38912              // 36864
#define SM_W  75776              // 37888 max
#define SM_DST 113664            // 512
#define SM_SG  114176            // 512
#define SMEM_TOT 114688

// paired-u64 lo layout: row r, k-step ks (16 halves), u64 slot s holds halves
// (16ks+2s, 16ks+2s+1 | 16ks+2s+8, 16ks+2s+9). Byte offset of element k in row:
__device__ __forceinline__ int lo_off(int k) {
    int ks = k >> 4, w = k & 15;
    return ks * 32 + ((w & 7) >> 1) * 8 + ((w >= 8) ? 4 : 0) + (k & 1) * 2;
}

// ---------------- asm helpers ----------------
__device__ __forceinline__ uint32_t smem_u32(const void* p) {
    uint32_t a;
    asm("{ .reg .u64 t; cvta.to.shared.u64 t, %1; cvt.u32.u64 %0, t; }" : "=r"(a) : "l"(p));
    return a;
}
__device__ __forceinline__ void ldsm4(uint32_t* r, uint32_t addr) {
    asm volatile("ldmatrix.sync.aligned.m8n8.x4.shared.b16 {%0,%1,%2,%3}, [%4];"
                 : "=r"(r[0]), "=r"(r[1]), "=r"(r[2]), "=r"(r[3]) : "r"(addr));
}
__device__ __forceinline__ void ldsm2(uint32_t* r, uint32_t addr) {
    asm volatile("ldmatrix.sync.aligned.m8n8.x2.shared.b16 {%0,%1}, [%2];"
                 : "=r"(r[0]), "=r"(r[1]) : "r"(addr));
}
__device__ __forceinline__ void mma16816(float* d, const uint32_t* a, const uint32_t* b) {
    asm volatile(
        "mma.sync.aligned.m16n8k16.row.col.f32.f16.f16.f32 "
        "{%0,%1,%2,%3}, {%4,%5,%6,%7}, {%8,%9}, {%0,%1,%2,%3};"
        : "+f"(d[0]), "+f"(d[1]), "+f"(d[2]), "+f"(d[3])
        : "r"(a[0]), "r"(a[1]), "r"(a[2]), "r"(a[3]), "r"(b[0]), "r"(b[1]));
}

// ---------------- misc ----------------
__device__ __forceinline__ void atomicMaxF(float* a, float v) {
    if (v >= 0.f) atomicMax((int*)a, __float_as_int(v));
    else          atomicMin((unsigned int*)a, (unsigned int)__float_as_int(v));
}
__device__ __forceinline__ void split2(float a, float b, uint32_t& hi, uint32_t& lo) {
    __half ha = __float2half_rn(a), hb = __float2half_rn(b);
    __half la = __float2half_rn(a - __half2float(ha));
    __half lb = __float2half_rn(b - __half2float(hb));
    hi = (uint32_t)__half_as_ushort(ha) | ((uint32_t)__half_as_ushort(hb) << 16);
    lo = (uint32_t)__half_as_ushort(la) | ((uint32_t)__half_as_ushort(lb) << 16);
}
// split 16 f32 -> hi uint4 x2 (halves 0..7, 8..15), lo likewise
__device__ __forceinline__ void split16(const float* p, bool fixinf,
                                        uint4& hA, uint4& hB, uint4& lA, uint4& lB) {
    float v[16];
    const float4* q = (const float4*)p;
    float4 a = q[0], b = q[1], c = q[2], d = q[3];
    v[0]=a.x; v[1]=a.y; v[2]=a.z; v[3]=a.w; v[4]=b.x; v[5]=b.y; v[6]=b.z; v[7]=b.w;
    v[8]=c.x; v[9]=c.y; v[10]=c.z; v[11]=c.w; v[12]=d.x; v[13]=d.y; v[14]=d.z; v[15]=d.w;
    if (fixinf) {
#pragma unroll
        for (int j = 0; j < 16; j++) if (!isfinite(v[j])) v[j] = 0.f;
    }
    uint32_t h[8], l[8];
#pragma unroll
    for (int j = 0; j < 8; j++) split2(v[2 * j], v[2 * j + 1], h[j], l[j]);
    hA = make_uint4(h[0], h[1], h[2], h[3]);
    hB = make_uint4(h[4], h[5], h[6], h[7]);
    lA = make_uint4(l[0], l[1], l[2], l[3]);
    lB = make_uint4(l[4], l[5], l[6], l[7]);
}
// store one 16-half k-group (hi contiguous, lo paired) at act row m, step ks
__device__ __forceinline__ void store_group(char* smc, int m, int ks,
                                            uint4 hA, uint4 hB, uint4 lA, uint4 lB) {
    *(uint4*)(smc + SM_AH + (m * LDH + ks * 16) * 2) = hA;
    *(uint4*)(smc + SM_AH + (m * LDH + ks * 16) * 2 + 16) = hB;
    *(uint4*)(smc + SM_AL + m * ALB + ks * 32) = make_uint4(lA.x, lB.x, lA.y, lB.y);
    *(uint4*)(smc + SM_AL + m * ALB + ks * 32 + 16) = make_uint4(lA.z, lB.z, lA.w, lB.w);
}
__device__ __forceinline__ void stageW(char* dst, const unsigned char* src, int bytes, int t) {
    for (int i = t * 16; i < bytes; i += NTHR * 16)
        *(uint4*)(dst + i) = *(const uint4*)(src + i);
}

// ---------------- core GEMM: acc += (Ah+Al)x(Wh+Wl), 3-term split ----------------
template<int K, int NW>
__device__ __forceinline__ void mma_compute(float (&acc)[NW / 8][2][4],
                                            const char* smc, uint32_t SB,
                                            int wLoff, int warp, int lane) {
    constexpr int NT = NW / 8;
    constexpr int WLDH = K + 8;
    constexpr int WLBP = (K == 64) ? 136 : 288;   // paired lo stride
    const int m0 = (warp & 3) * 32;
    const int n0 = (warp >> 2) * NW;
    const int arow = m0 + (lane & 7) + ((lane >> 3) & 1) * 8;
    const int acol8 = (lane >> 4) * 8;
    const int brow = lane & 7;
    const int bk8 = ((lane >> 3) & 1) * 8;
    const int rq = lane >> 2, cq = 2 * (lane & 3);
    const int slotB = (cq >> 1) * 8;
    const uint32_t aHb = SB + SM_AH;
    const uint32_t wHb = SB + SM_W;
    const char* aLp = smc + SM_AL;
    const char* wLp = smc + SM_W + wLoff;

#pragma unroll 1
    for (int k0 = 0; k0 < K; k0 += 16) {
        const int ks32 = (k0 >> 4) * 32;
        uint32_t ah[2][4], al[2][4];
#pragma unroll
        for (int mt = 0; mt < 2; mt++) {
            ldsm4(ah[mt], aHb + (uint32_t)((arow + mt * 16) * LDH + k0 + acol8) * 2);
            int r0 = m0 + mt * 16 + rq;
            uint2 p0 = *(const uint2*)(aLp + r0 * ALB + ks32 + slotB);
            uint2 p1 = *(const uint2*)(aLp + (r0 + 8) * ALB + ks32 + slotB);
            al[mt][0] = p0.x; al[mt][2] = p0.y;
            al[mt][1] = p1.x; al[mt][3] = p1.y;
        }
#pragma unroll
        for (int nt = 0; nt < NT; nt++) {
            uint32_t bh[2], bl[2];
            ldsm2(bh, wHb + (uint32_t)((n0 + nt * 8 + brow) * WLDH + k0 + bk8) * 2);
            int bn = n0 + nt * 8 + rq;
            uint2 pb = *(const uint2*)(wLp + bn * WLBP + ks32 + slotB);
            bl[0] = pb.x; bl[1] = pb.y;
#pragma unroll
            for (int mt = 0; mt < 2; mt++) {
                mma16816(acc[nt][mt], ah[mt], bh);
                mma16816(acc[nt][mt], ah[mt], bl);
                mma16816(acc[nt][mt], al[mt], bh);
            }
        }
    }
}

template<int NW, int NREAL>
__device__ __forceinline__ void init_bias(float (&acc)[NW / 8][2][4],
                                          const float* __restrict__ bias, int warp, int lane) {
    const int n0 = (warp >> 2) * NW;
    const int cq = 2 * (lane & 3);
#pragma unroll
    for (int nt = 0; nt < NW / 8; nt++) {
        int c = n0 + nt * 8 + cq;
        float b0 = (c < NREAL) ? bias[c] : 0.f;
        float b1 = (c + 1 < NREAL) ? bias[c + 1] : 0.f;
#pragma unroll
        for (int mt = 0; mt < 2; mt++) {
            acc[nt][mt][0] = b0; acc[nt][mt][1] = b1;
            acc[nt][mt][2] = b0; acc[nt][mt][3] = b1;
        }
    }
}

// register epilogue: leaky-relu + split + store to act tiles.
// MUST be preceded by __syncthreads().
template<int NW, bool RELU>
__device__ __forceinline__ void epi_split(float (&acc)[NW / 8][2][4],
                                          char* smc, int warp, int lane) {
    const int m0 = (warp & 3) * 32;
    const int n0 = (warp >> 2) * NW;
    const int rq = lane >> 2, cq = 2 * (lane & 3);
#pragma unroll
    for (int nt = 0; nt < NW / 8; nt++) {
#pragma unroll
        for (int mt = 0; mt < 2; mt++) {
            int r = m0 + mt * 16 + rq;
            int c = n0 + nt * 8 + cq;
            float v0 = acc[nt][mt][0], v1 = acc[nt][mt][1];
            float v2 = acc[nt][mt][2], v3 = acc[nt][mt][3];
            if (RELU) {
                v0 = fmaxf(v0, 0.2f * v0); v1 = fmaxf(v1, 0.2f * v1);
                v2 = fmaxf(v2, 0.2f * v2); v3 = fmaxf(v3, 0.2f * v3);
            }
            uint32_t h01, l01, h23, l23;
            split2(v0, v1, h01, l01);
            split2(v2, v3, h23, l23);
            int off = lo_off(c);
            *(uint32_t*)(smc + SM_AH + (r * LDH + c) * 2) = h01;
            *(uint32_t*)(smc + SM_AH + ((r + 8) * LDH + c) * 2) = h23;
            *(uint32_t*)(smc + SM_AL + r * ALB + off) = l01;
            *(uint32_t*)(smc + SM_AL + (r + 8) * ALB + off) = l23;
        }
    }
}

// ---------------- prep / init ----------------
__device__ void fill_layer(int tid, int stride, int baseB, const float* __restrict__ W,
                           int Kr, int Nr, int Np) {
    int Kp = Kr + 8;
    for (int i = tid; i < Np * Kp; i += stride) {
        int n = i / Kp, k = i - n * Kp;
        float v = (k < Kr && n < Nr) ? W[k * Nr + n] : 0.f;
        *(__half*)(g_wimg + baseB + i * 2) = __float2half_rn(v);
    }
    int loB = baseB + Np * Kp * 2;
    int strideB = (Kr == 64) ? 136 : 288;
    for (int i = tid; i < Np * Kr; i += stride) {
        int n = i / Kr, k = i - n * Kr;
        float v = (n < Nr) ? W[k * Nr + n] : 0.f;
        __half h = __float2half_rn(v);
        __half l = __float2half_rn(v - __half2float(h));
        *(__half*)(g_wimg + loB + n * strideB + lo_off(k)) = l;
    }
}

extern "C" __global__ void prep_kernel(const float* Wm1, const float* Wm2,
                                       const float* Wm3, const float* Wm4,
                                       const float* Wr1, const float* Wr2,
                                       const float* Wr3, const float* Wr4) {
    int tid = blockIdx.x * blockDim.x + threadIdx.x;
    int stride = gridDim.x * blockDim.x;
    fill_layer(tid, stride, WO_E1, Wm1, 144, 64, 64);
    fill_layer(tid, stride, WO_E2, Wm2, 64, 128, 128);
    fill_layer(tid, stride, WO_E3, Wm3, 128, 64, 64);
    fill_layer(tid, stride, WO_E4, Wm4, 64, 65, 80);
    fill_layer(tid, stride, WO_N1, Wr1, 128, 64, 64);
    fill_layer(tid, stride, WO_N2, Wr2, 64, 128, 128);
    fill_layer(tid, stride, WO_N3, Wr3, 128, 64, 64);
    fill_layer(tid, stride, WO_N4, Wr4, 64, 64, 64);
}

extern "C" __global__ void prep_nf_kernel(const float* __restrict__ nf) {
    int i = blockIdx.x * blockDim.x + threadIdx.x;
    if (i < NN * 64) {
        float v = nf[i];
        __half h = __float2half_rn(v);
        g_nfh[i] = h;
        g_nfl[i] = __float2half_rn(v - __half2float(h));
    }
}

extern "C" __global__ void init1_kernel() {
    int i = blockIdx.x * blockDim.x + threadIdx.x;
    if (i < NN * 32) g_nf1[i] = 0.f;
}
extern "C" __global__ void init2_kernel() {
    int i = blockIdx.x * blockDim.x + threadIdx.x;
    if (i < NN * 32) g_nf2[i] = -INFINITY;
}

// ---------------- edge kernel ----------------
extern "C" __global__ void __launch_bounds__(NTHR, 2)
edge_kernel(const float* __restrict__ ef,
            const int* __restrict__ src, const int* __restrict__ dst,
            const float* __restrict__ bm1, const float* __restrict__ bm2,
            const float* __restrict__ bm3, const float* __restrict__ bm4) {
    extern __shared__ char smc[];
    const uint32_t SB = smem_u32(smc);
    int* sdst = (int*)(smc + SM_DST);
    float* sg = (float*)(smc + SM_SG);
    const int t = threadIdx.x, warp = t >> 5, lane = t & 31;
    const int e0 = blockIdx.x * 128;

    if (t < 128) sdst[t] = dst[e0 + t];

    // gather X = [nf[src](presplit) | nf[dst](presplit) | ef(runtime split)]
    for (int idx = t; idx < 128 * 9; idx += NTHR) {
        int m = idx / 9, ks = idx - m * 9;
        uint4 hA, hB, lA, lB;
        if (ks < 8) {
            int node = (ks < 4) ? src[e0 + m] : dst[e0 + m];
            int k16 = (ks & 3) * 16;
            const uint4* ph = (const uint4*)(g_nfh + (size_t)node * 64 + k16);
            const uint4* pl = (const uint4*)(g_nfl + (size_t)node * 64 + k16);
            hA = ph[0]; hB = ph[1]; lA = pl[0]; lB = pl[1];
        } else {
            split16(ef + (size_t)(e0 + m) * 16, false, hA, hB, lA, lB);
        }
        store_group(smc, m, ks, hA, hB, lA, lB);
    }
    stageW(smc + SM_W, g_wimg + WO_E1, WT_E1, t);
    __syncthreads();

    { // L1: 144 -> 64
        float acc[4][2][4];
        init_bias<32, 64>(acc, bm1, warp, lane);
        mma_compute<144, 32>(acc, smc, SB, WH_E1, warp, lane);
        __syncthreads();
        epi_split<32, true>(acc, smc, warp, lane);
        stageW(smc + SM_W, g_wimg + WO_E2, WT_E2, t);
    }
    __syncthreads();

    { // L2: 64 -> 128
        float acc[8][2][4];
        init_bias<64, 128>(acc, bm2, warp, lane);
        mma_compute<64, 64>(acc, smc, SB, WH_E2, warp, lane);
        __syncthreads();
        epi_split<64, true>(acc, smc, warp, lane);
        stageW(smc + SM_W, g_wimg + WO_E3, WT_E3, t);
    }
    __syncthreads();

    { // L3: 128 -> 64
        float acc[4][2][4];
        init_bias<32, 64>(acc, bm3, warp, lane);
        mma_compute<128, 32>(acc, smc, SB, WH_E3, warp, lane);
        __syncthreads();
        epi_split<32, true>(acc, smc, warp, lane);
        stageW(smc + SM_W, g_wimg + WO_E4, WT_E4, t);
    }
    __syncthreads();

    { // L4: 64 -> 80 (col0 gate, 1..64 feats, 65..79 pad)
        float acc[5][2][4];
        init_bias<40, 65>(acc, bm4, warp, lane);
        mma_compute<64, 40>(acc, smc, SB, WH_E4, warp, lane);

        const int m0 = (warp & 3) * 32;
        const int n0 = (warp >> 2) * 40;
        const int rq = lane >> 2, cq = 2 * (lane & 3);
        if ((warp >> 2) == 0 && (lane & 3) == 0) {
#pragma unroll
            for (int mt = 0; mt < 2; mt++) {
                int r = m0 + mt * 16 + rq;
                sg[r] = 1.f / (1.f + expf(-acc[0][mt][0]));
                sg[r + 8] = 1.f / (1.f + expf(-acc[0][mt][2]));
            }
        }
        __syncthreads();
#pragma unroll
        for (int nt = 0; nt < 5; nt++) {
#pragma unroll
            for (int mt = 0; mt < 2; mt++) {
#pragma unroll
                for (int e = 0; e < 4; e++) {
                    int col = n0 + nt * 8 + cq + (e & 1);
                    int row = m0 + mt * 16 + rq + (e >> 1) * 8;
                    if (col >= 1 && col <= 64) {
                        float val = acc[nt][mt][e] * sg[row];
                        int d = sdst[row];
                        int h = col - 1;
                        if (h < 32) atomicAdd(&g_nf1[d * 32 + h], val);
                        else        atomicMaxF(&g_nf2[d * 32 + h - 32], val);
                    }
                }
            }
        }
    }
}

// ---------------- node kernel ----------------
extern "C" __global__ void __launch_bounds__(NTHR, 2)
node_kernel(const float* __restrict__ br1, const float* __restrict__ br2,
            const float* __restrict__ br3, const float* __restrict__ br4,
            float* __restrict__ out) {
    extern __shared__ char smc[];
    const uint32_t SB = smem_u32(smc);
    const int t = threadIdx.x, warp = t >> 5, lane = t & 31;
    const int n0g = blockIdx.x * 128;
    const int cnt = min(128, NN - n0g);

    // gather Y = [nf(presplit) | nf1(split) | nf2(split+fix)]
    for (int idx = t; idx < 128 * 8; idx += NTHR) {
        int m = idx >> 3, ks = idx & 7;
        int nd = n0g + min(m, cnt - 1);
        uint4 hA, hB, lA, lB;
        if (ks < 4) {
            const uint4* ph = (const uint4*)(g_nfh + (size_t)nd * 64 + ks * 16);
            const uint4* pl = (const uint4*)(g_nfl + (size_t)nd * 64 + ks * 16);
            hA = ph[0]; hB = ph[1]; lA = pl[0]; lB = pl[1];
        } else if (ks < 6) {
            split16(g_nf1 + (size_t)nd * 32 + (ks - 4) * 16, false, hA, hB, lA, lB);
        } else {
            split16(g_nf2 + (size_t)nd * 32 + (ks - 6) * 16, true, hA, hB, lA, lB);
        }
        store_group(smc, m, ks, hA, hB, lA, lB);
    }
    stageW(smc + SM_W, g_wimg + WO_N1, WT_N1, t);
    __syncthreads();

    { float acc[4][2][4];
      init_bias<32, 64>(acc, br1, warp, lane);
      mma_compute<128, 32>(acc, smc, SB, WH_N1, warp, lane);
      __syncthreads();
      epi_split<32, true>(acc, smc, warp, lane);
      stageW(smc + SM_W, g_wimg + WO_N2, WT_N2, t); }
    __syncthreads();

    { float acc[8][2][4];
      init_bias<64, 128>(acc, br2, warp, lane);
      mma_compute<64, 64>(acc, smc, SB, WH_N2, warp, lane);
      __syncthreads();
      epi_split<64, true>(acc, smc, warp, lane);
      stageW(smc + SM_W, g_wimg + WO_N3, WT_N3, t); }
    __syncthreads();

    { float acc[4][2][4];
      init_bias<32, 64>(acc, br3, warp, lane);
      mma_compute<128, 32>(acc, smc, SB, WH_N3, warp, lane);
      __syncthreads();
      epi_split<32, true>(acc, smc, warp, lane);
      stageW(smc + SM_W, g_wimg + WO_N4, WT_N4, t); }
    __syncthreads();

    { // final: 64 -> 64, store f32 to out
        float acc[4][2][4];
        init_bias<32, 64>(acc, br4, warp, lane);
        mma_compute<64, 32>(acc, smc, SB, WH_N4, warp, lane);
        const int m0 = (warp & 3) * 32;
        const int n0 = (warp >> 2) * 32;
        const int rq = lane >> 2, cq = 2 * (lane & 3);
#pragma unroll
        for (int nt = 0; nt < 4; nt++) {
#pragma unroll
            for (int mt = 0; mt < 2; mt++) {
#pragma unroll
                for (int e = 0; e < 4; e++) {
                    int col = n0 + nt * 8 + cq + (e & 1);
                    int row = m0 + mt * 16 + rq + (e >> 1) * 8;
                    if (row < cnt)
                        out[(size_t)(n0g + row) * 64 + col] = acc[nt][mt][e];
                }
            }
        }
    }
}

// ---------------- launch ----------------
extern "C" void kernel_launch(void* const* d_in, const int* in_sizes, int n_in,
                              void* d_out, int out_size) {
    (void)in_sizes; (void)n_in; (void)out_size;
    const float* nf = (const float*)d_in[0];
    const float* ef = (const float*)d_in[1];
    const int* src  = (const int*)d_in[2];
    const int* dst  = (const int*)d_in[3];

    cudaFuncSetAttribute(edge_kernel, cudaFuncAttributeMaxDynamicSharedMemorySize, SMEM_TOT);
    cudaFuncSetAttribute(node_kernel, cudaFuncAttributeMaxDynamicSharedMemorySize, SMEM_TOT);

    prep_kernel<<<128, 256>>>(
        (const float*)d_in[4], (const float*)d_in[6],
        (const float*)d_in[8], (const float*)d_in[10],
        (const float*)d_in[12], (const float*)d_in[14],
        (const float*)d_in[16], (const float*)d_in[18]);
    prep_nf_kernel<<<(NN * 64 + 255) / 256, 256>>>(nf);
    init1_kernel<<<(NN * 32 + 255) / 256, 256>>>();
    init2_kernel<<<(NN * 32 + 255) / 256, 256>>>();

    edge_kernel<<<NE / 128, NTHR, SMEM_TOT>>>(
        ef, src, dst,
        (const float*)d_in[5], (const float*)d_in[7],
        (const float*)d_in[9], (const float*)d_in[11]);

    node_kernel<<<(NN + 127) / 128, NTHR, SMEM_TOT>>>(
        (const float*)d_in[13], (const float*)d_in[15],
        (const float*)d_in[17], (const float*)d_in[19],
        (float*)d_out);
}

// round 15
// speedup vs baseline: 3.6281x; 1.1804x over previous
#include <cuda_runtime.h>
#include <cuda_fp16.h>
#include <math.h>
#include <stdint.h>

#define NN 50000
#define NE 1600000
#define NTHR 256

// ---------------- device scratch ----------------
__device__ float g_nf1[NN * 32];
__device__ float g_nf2[NN * 32];
__device__ __align__(16) __half g_nfh[NN * 64];   // nf fp16 hi
__device__ __align__(16) __half g_nfl[NN * 64];   // nf fp16 lo

// Weight images per layer: [hi padded: Np x (Kr+8) halves, ldmatrix-friendly]
// then [lo: Np rows, paired-u64 layout, stride 136B (K=64) / 288B (K=128/144)].
#define WO_E1 0
#define WO_E2 37888
#define WO_E3 73728
#define WO_E4 109568
#define WO_N1 131968
#define WO_N2 167808
#define WO_N3 203648
#define WO_N4 239488
#define W_IMG_TOTAL 257408
__device__ __align__(16) unsigned char g_wimg[W_IMG_TOTAL];

#define WH_E1 19456
#define WH_E2 18432
#define WH_E3 17408
#define WH_E4 11520
#define WH_N1 17408
#define WH_N2 18432
#define WH_N3 17408
#define WH_N4 9216
#define WT_E1 37888
#define WT_E2 35840
#define WT_E3 35840
#define WT_E4 22400
#define WT_N1 35840
#define WT_N2 35840
#define WT_N3 35840
#define WT_N4 17920

// ---------------- smem layout (bytes) ----------------
#define LDH 152                  // act-hi halves/row (304B, conflict-free ldmatrix)
#define ALB 288                  // act-lo row bytes, paired-u64 layout
#define SM_AH 0                  // 38912
#define SM_AL 38912              // 36864
#define SM_W  75776              // 37888 max
#define SM_DST 113664            // 512
#define SM_SG  114176            // 512
#define SMEM_TOT 114688

// paired-u64 lo layout: row r, k-step ks (16 halves), u64 slot s holds halves
// (16ks+2s, 16ks+2s+1 | 16ks+2s+8, 16ks+2s+9).
__device__ __forceinline__ int lo_off(int k) {
    int ks = k >> 4, w = k & 15;
    return ks * 32 + ((w & 7) >> 1) * 8 + ((w >= 8) ? 4 : 0) + (k & 1) * 2;
}

// ---------------- asm helpers ----------------
__device__ __forceinline__ uint32_t smem_u32(const void* p) {
    uint32_t a;
    asm("{ .reg .u64 t; cvta.to.shared.u64 t, %1; cvt.u32.u64 %0, t; }" : "=r"(a) : "l"(p));
    return a;
}
__device__ __forceinline__ void ldsm4(uint32_t* r, uint32_t addr) {
    asm volatile("ldmatrix.sync.aligned.m8n8.x4.shared.b16 {%0,%1,%2,%3}, [%4];"
                 : "=r"(r[0]), "=r"(r[1]), "=r"(r[2]), "=r"(r[3]) : "r"(addr));
}
__device__ __forceinline__ void ldsm2(uint32_t* r, uint32_t addr) {
    asm volatile("ldmatrix.sync.aligned.m8n8.x2.shared.b16 {%0,%1}, [%2];"
                 : "=r"(r[0]), "=r"(r[1]) : "r"(addr));
}
__device__ __forceinline__ void mma16816(float* d, const uint32_t* a, const uint32_t* b) {
    asm volatile(
        "mma.sync.aligned.m16n8k16.row.col.f32.f16.f16.f32 "
        "{%0,%1,%2,%3}, {%4,%5,%6,%7}, {%8,%9}, {%0,%1,%2,%3};"
        : "+f"(d[0]), "+f"(d[1]), "+f"(d[2]), "+f"(d[3])
        : "r"(a[0]), "r"(a[1]), "r"(a[2]), "r"(a[3]), "r"(b[0]), "r"(b[1]));
}
__device__ __forceinline__ void cpasync16(uint32_t dstS, const void* src) {
    asm volatile("cp.async.cg.shared.global [%0], [%1], 16;"
                 :: "r"(dstS), "l"(src));
}
__device__ __forceinline__ void cpasync_wait() {
    asm volatile("cp.async.commit_group;\n\tcp.async.wait_group 0;" ::: "memory");
}

// ---------------- misc ----------------
__device__ __forceinline__ void atomicMaxF(float* a, float v) {
    if (v >= 0.f) atomicMax((int*)a, __float_as_int(v));
    else          atomicMin((unsigned int*)a, (unsigned int)__float_as_int(v));
}
__device__ __forceinline__ void split2(float a, float b, uint32_t& hi, uint32_t& lo) {
    __half ha = __float2half_rn(a), hb = __float2half_rn(b);
    __half la = __float2half_rn(a - __half2float(ha));
    __half lb = __float2half_rn(b - __half2float(hb));
    hi = (uint32_t)__half_as_ushort(ha) | ((uint32_t)__half_as_ushort(hb) << 16);
    lo = (uint32_t)__half_as_ushort(la) | ((uint32_t)__half_as_ushort(lb) << 16);
}
__device__ __forceinline__ void split16(const float* p, bool fixinf,
                                        uint4& hA, uint4& hB, uint4& lA, uint4& lB) {
    float v[16];
    const float4* q = (const float4*)p;
    float4 a = q[0], b = q[1], c = q[2], d = q[3];
    v[0]=a.x; v[1]=a.y; v[2]=a.z; v[3]=a.w; v[4]=b.x; v[5]=b.y; v[6]=b.z; v[7]=b.w;
    v[8]=c.x; v[9]=c.y; v[10]=c.z; v[11]=c.w; v[12]=d.x; v[13]=d.y; v[14]=d.z; v[15]=d.w;
    if (fixinf) {
#pragma unroll
        for (int j = 0; j < 16; j++) if (!isfinite(v[j])) v[j] = 0.f;
    }
    uint32_t h[8], l[8];
#pragma unroll
    for (int j = 0; j < 8; j++) split2(v[2 * j], v[2 * j + 1], h[j], l[j]);
    hA = make_uint4(h[0], h[1], h[2], h[3]);
    hB = make_uint4(h[4], h[5], h[6], h[7]);
    lA = make_uint4(l[0], l[1], l[2], l[3]);
    lB = make_uint4(l[4], l[5], l[6], l[7]);
}
__device__ __forceinline__ void store_group(char* smc, int m, int ks,
                                            uint4 hA, uint4 hB, uint4 lA, uint4 lB) {
    *(uint4*)(smc + SM_AH + (m * LDH + ks * 16) * 2) = hA;
    *(uint4*)(smc + SM_AH + (m * LDH + ks * 16) * 2 + 16) = hB;
    *(uint4*)(smc + SM_AL + m * ALB + ks * 32) = make_uint4(lA.x, lB.x, lA.y, lB.y);
    *(uint4*)(smc + SM_AL + m * ALB + ks * 32 + 16) = make_uint4(lA.z, lB.z, lA.w, lB.w);
}
__device__ __forceinline__ void stageW(uint32_t dstS, const unsigned char* src, int bytes, int t) {
    for (int i = t * 16; i < bytes; i += NTHR * 16)
        cpasync16(dstS + i, src + i);
}

// ---------------- core GEMM step: acc += (Ah+Al)x(Wh+Wl), 3-term split ----------------
template<int K, int NW>
__device__ __forceinline__ void mma_step(int k0, float (&acc)[NW / 8][2][4],
                                         uint32_t aH, const char* aL,
                                         uint32_t wH, const char* wL) {
    constexpr int NT = NW / 8;
    constexpr int WLDH = K + 8;
    constexpr int WLBP = (K == 64) ? 136 : 288;
    const int ks32 = (k0 >> 4) * 32;
    uint32_t ah[2][4], al[2][4];
#pragma unroll
    for (int mt = 0; mt < 2; mt++) {
        ldsm4(ah[mt], aH + (uint32_t)(mt * 16 * LDH + k0) * 2);
        uint2 p0 = *(const uint2*)(aL + mt * 16 * ALB + ks32);
        uint2 p1 = *(const uint2*)(aL + (mt * 16 + 8) * ALB + ks32);
        al[mt][0] = p0.x; al[mt][2] = p0.y;
        al[mt][1] = p1.x; al[mt][3] = p1.y;
    }
#pragma unroll
    for (int nt = 0; nt < NT; nt++) {
        uint32_t bh[2], bl[2];
        ldsm2(bh, wH + (uint32_t)(nt * 8 * WLDH + k0) * 2);
        uint2 pb = *(const uint2*)(wL + nt * 8 * WLBP + ks32);
        bl[0] = pb.x; bl[1] = pb.y;
#pragma unroll
        for (int mt = 0; mt < 2; mt++) {
            mma16816(acc[nt][mt], ah[mt], bh);
            mma16816(acc[nt][mt], ah[mt], bl);
            mma16816(acc[nt][mt], al[mt], bh);
        }
    }
}

template<int K, int NW>
__device__ __forceinline__ void mma_compute(float (&acc)[NW / 8][2][4],
                                            const char* smc, uint32_t SB,
                                            int wLoff, int warp, int lane) {
    constexpr int WLDH = K + 8;
    constexpr int WLBP = (K == 64) ? 136 : 288;
    const int m0 = (warp & 3) * 32;
    const int n0 = (warp >> 2) * NW;
    const int arow = m0 + (lane & 7) + ((lane >> 3) & 1) * 8;
    const int acol8 = (lane >> 4) * 8;
    const int brow = lane & 7;
    const int bk8 = ((lane >> 3) & 1) * 8;
    const int rq = lane >> 2, cq = 2 * (lane & 3);
    const int slotB = (cq >> 1) * 8;
    const uint32_t aH = SB + SM_AH + (uint32_t)(arow * LDH + acol8) * 2;
    const char* aL = smc + SM_AL + (m0 + rq) * ALB + slotB;
    const uint32_t wH = SB + SM_W + (uint32_t)((n0 + brow) * WLDH + bk8) * 2;
    const char* wL = smc + SM_W + wLoff + (n0 + rq) * WLBP + slotB;

    if constexpr (NW <= 40) {
#pragma unroll
        for (int k0 = 0; k0 < K; k0 += 16)
            mma_step<K, NW>(k0, acc, aH, aL, wH, wL);
    } else {
#pragma unroll 2
        for (int k0 = 0; k0 < K; k0 += 16)
            mma_step<K, NW>(k0, acc, aH, aL, wH, wL);
    }
}

template<int NW, int NREAL>
__device__ __forceinline__ void init_bias(float (&acc)[NW / 8][2][4],
                                          const float* __restrict__ bias, int warp, int lane) {
    const int n0 = (warp >> 2) * NW;
    const int cq = 2 * (lane & 3);
#pragma unroll
    for (int nt = 0; nt < NW / 8; nt++) {
        int c = n0 + nt * 8 + cq;
        float b0 = (c < NREAL) ? bias[c] : 0.f;
        float b1 = (c + 1 < NREAL) ? bias[c + 1] : 0.f;
#pragma unroll
        for (int mt = 0; mt < 2; mt++) {
            acc[nt][mt][0] = b0; acc[nt][mt][1] = b1;
            acc[nt][mt][2] = b0; acc[nt][mt][3] = b1;
        }
    }
}

// register epilogue: leaky-relu + split + store to act tiles.
// MUST be preceded by __syncthreads().
template<int NW, bool RELU>
__device__ __forceinline__ void epi_split(float (&acc)[NW / 8][2][4],
                                          char* smc, int warp, int lane) {
    const int m0 = (warp & 3) * 32;
    const int n0 = (warp >> 2) * NW;
    const int rq = lane >> 2, cq = 2 * (lane & 3);
#pragma unroll
    for (int nt = 0; nt < NW / 8; nt++) {
#pragma unroll
        for (int mt = 0; mt < 2; mt++) {
            int r = m0 + mt * 16 + rq;
            int c = n0 + nt * 8 + cq;
            float v0 = acc[nt][mt][0], v1 = acc[nt][mt][1];
            float v2 = acc[nt][mt][2], v3 = acc[nt][mt][3];
            if (RELU) {
                v0 = fmaxf(v0, 0.2f * v0); v1 = fmaxf(v1, 0.2f * v1);
                v2 = fmaxf(v2, 0.2f * v2); v3 = fmaxf(v3, 0.2f * v3);
            }
            uint32_t h01, l01, h23, l23;
            split2(v0, v1, h01, l01);
            split2(v2, v3, h23, l23);
            int off = lo_off(c);
            *(uint32_t*)(smc + SM_AH + (r * LDH + c) * 2) = h01;
            *(uint32_t*)(smc + SM_AH + ((r + 8) * LDH + c) * 2) = h23;
            *(uint32_t*)(smc + SM_AL + r * ALB + off) = l01;
            *(uint32_t*)(smc + SM_AL + (r + 8) * ALB + off) = l23;
        }
    }
}

// ---------------- prep / init ----------------
__device__ void fill_layer(int tid, int stride, int baseB, const float* __restrict__ W,
                           int Kr, int Nr, int Np) {
    int Kp = Kr + 8;
    for (int i = tid; i < Np * Kp; i += stride) {
        int n = i / Kp, k = i - n * Kp;
        float v = (k < Kr && n < Nr) ? W[k * Nr + n] : 0.f;
        *(__half*)(g_wimg + baseB + i * 2) = __float2half_rn(v);
    }
    int loB = baseB + Np * Kp * 2;
    int strideB = (Kr == 64) ? 136 : 288;
    for (int i = tid; i < Np * Kr; i += stride) {
        int n = i / Kr, k = i - n * Kr;
        float v = (n < Nr) ? W[k * Nr + n] : 0.f;
        __half h = __float2half_rn(v);
        __half l = __float2half_rn(v - __half2float(h));
        *(__half*)(g_wimg + loB + n * strideB + lo_off(k)) = l;
    }
}

extern "C" __global__ void prep_kernel(const float* Wm1, const float* Wm2,
                                       const float* Wm3, const float* Wm4,
                                       const float* Wr1, const float* Wr2,
                                       const float* Wr3, const float* Wr4) {
    int tid = blockIdx.x * blockDim.x + threadIdx.x;
    int stride = gridDim.x * blockDim.x;
    fill_layer(tid, stride, WO_E1, Wm1, 144, 64, 64);
    fill_layer(tid, stride, WO_E2, Wm2, 64, 128, 128);
    fill_layer(tid, stride, WO_E3, Wm3, 128, 64, 64);
    fill_layer(tid, stride, WO_E4, Wm4, 64, 65, 80);
    fill_layer(tid, stride, WO_N1, Wr1, 128, 64, 64);
    fill_layer(tid, stride, WO_N2, Wr2, 64, 128, 128);
    fill_layer(tid, stride, WO_N3, Wr3, 128, 64, 64);
    fill_layer(tid, stride, WO_N4, Wr4, 64, 64, 64);
}

extern "C" __global__ void prep_nf_kernel(const float* __restrict__ nf) {
    int i = blockIdx.x * blockDim.x + threadIdx.x;
    if (i < NN * 64) {
        float v = nf[i];
        __half h = __float2half_rn(v);
        g_nfh[i] = h;
        g_nfl[i] = __float2half_rn(v - __half2float(h));
    }
}

extern "C" __global__ void init1_kernel() {
    int i = blockIdx.x * blockDim.x + threadIdx.x;
    if (i < NN * 32) g_nf1[i] = 0.f;
}
extern "C" __global__ void init2_kernel() {
    int i = blockIdx.x * blockDim.x + threadIdx.x;
    if (i < NN * 32) g_nf2[i] = -INFINITY;
}

// ---------------- edge kernel ----------------
extern "C" __global__ void __launch_bounds__(NTHR, 2)
edge_kernel(const float* __restrict__ ef,
            const int* __restrict__ src, const int* __restrict__ dst,
            const float* __restrict__ bm1, const float* __restrict__ bm2,
            const float* __restrict__ bm3, const float* __restrict__ bm4) {
    extern __shared__ char smc[];
    const uint32_t SB = smem_u32(smc);
    int* sdst = (int*)(smc + SM_DST);
    float* sg = (float*)(smc + SM_SG);
    const int t = threadIdx.x, warp = t >> 5, lane = t & 31;
    const int e0 = blockIdx.x * 128;

    if (t < 128) sdst[t] = dst[e0 + t];

    // gather X = [nf[src](presplit) | nf[dst](presplit) | ef(runtime split)]
    for (int idx = t; idx < 128 * 9; idx += NTHR) {
        int m = idx / 9, ks = idx - m * 9;
        uint4 hA, hB, lA, lB;
        if (ks < 8) {
            int node = (ks < 4) ? src[e0 + m] : dst[e0 + m];
            int k16 = (ks & 3) * 16;
            const uint4* ph = (const uint4*)(g_nfh + (size_t)node * 64 + k16);
            const uint4* pl = (const uint4*)(g_nfl + (size_t)node * 64 + k16);
            hA = ph[0]; hB = ph[1]; lA = pl[0]; lB = pl[1];
        } else {
            split16(ef + (size_t)(e0 + m) * 16, false, hA, hB, lA, lB);
        }
        store_group(smc, m, ks, hA, hB, lA, lB);
    }
    stageW(SB + SM_W, g_wimg + WO_E1, WT_E1, t);
    cpasync_wait();
    __syncthreads();

    { // L1: 144 -> 64
        float acc[4][2][4];
        init_bias<32, 64>(acc, bm1, warp, lane);
        mma_compute<144, 32>(acc, smc, SB, WH_E1, warp, lane);
        __syncthreads();
        epi_split<32, true>(acc, smc, warp, lane);
        stageW(SB + SM_W, g_wimg + WO_E2, WT_E2, t);
        cpasync_wait();
    }
    __syncthreads();

    { // L2: 64 -> 128
        float acc[8][2][4];
        init_bias<64, 128>(acc, bm2, warp, lane);
        mma_compute<64, 64>(acc, smc, SB, WH_E2, warp, lane);
        __syncthreads();
        epi_split<64, true>(acc, smc, warp, lane);
        stageW(SB + SM_W, g_wimg + WO_E3, WT_E3, t);
        cpasync_wait();
    }
    __syncthreads();

    { // L3: 128 -> 64
        float acc[4][2][4];
        init_bias<32, 64>(acc, bm3, warp, lane);
        mma_compute<128, 32>(acc, smc, SB, WH_E3, warp, lane);
        __syncthreads();
        epi_split<32, true>(acc, smc, warp, lane);
        stageW(SB + SM_W, g_wimg + WO_E4, WT_E4, t);
        cpasync_wait();
    }
    __syncthreads();

    { // L4: 64 -> 80 (col0 gate, 1..64 feats, 65..79 pad)
        float acc[5][2][4];
        init_bias<40, 65>(acc, bm4, warp, lane);
        mma_compute<64, 40>(acc, smc, SB, WH_E4, warp, lane);

        const int m0 = (warp & 3) * 32;
        const int n0 = (warp >> 2) * 40;
        const int rq = lane >> 2, cq = 2 * (lane & 3);
        if ((warp >> 2) == 0 && (lane & 3) == 0) {
#pragma unroll
            for (int mt = 0; mt < 2; mt++) {
                int r = m0 + mt * 16 + rq;
                sg[r] = 1.f / (1.f + expf(-acc[0][mt][0]));
                sg[r + 8] = 1.f / (1.f + expf(-acc[0][mt][2]));
            }
        }
        __syncthreads();
#pragma unroll
        for (int nt = 0; nt < 5; nt++) {
#pragma unroll
            for (int mt = 0; mt < 2; mt++) {
#pragma unroll
                for (int e = 0; e < 4; e++) {
                    int col = n0 + nt * 8 + cq + (e & 1);
                    int row = m0 + mt * 16 + rq + (e >> 1) * 8;
                    if (col >= 1 && col <= 64) {
                        float val = acc[nt][mt][e] * sg[row];
                        int d = sdst[row];
                        int h = col - 1;
                        if (h < 32) atomicAdd(&g_nf1[d * 32 + h], val);
                        else        atomicMaxF(&g_nf2[d * 32 + h - 32], val);
                    }
                }
            }
        }
    }
}

// ---------------- node kernel ----------------
extern "C" __global__ void __launch_bounds__(NTHR, 2)
node_kernel(const float* __restrict__ br1, const float* __restrict__ br2,
            const float* __restrict__ br3, const float* __restrict__ br4,
            float* __restrict__ out) {
    extern __shared__ char smc[];
    const uint32_t SB = smem_u32(smc);
    const int t = threadIdx.x, warp = t >> 5, lane = t & 31;
    const int n0g = blockIdx.x * 128;
    const int cnt = min(128, NN - n0g);

    // gather Y = [nf(presplit) | nf1(split) | nf2(split+fix)]
    for (int idx = t; idx < 128 * 8; idx += NTHR) {
        int m = idx >> 3, ks = idx & 7;
        int nd = n0g + min(m, cnt - 1);
        uint4 hA, hB, lA, lB;
        if (ks < 4) {
            const uint4* ph = (const uint4*)(g_nfh + (size_t)nd * 64 + ks * 16);
            const uint4* pl = (const uint4*)(g_nfl + (size_t)nd * 64 + ks * 16);
            hA = ph[0]; hB = ph[1]; lA = pl[0]; lB = pl[1];
        } else if (ks < 6) {
            split16(g_nf1 + (size_t)nd * 32 + (ks - 4) * 16, false, hA, hB, lA, lB);
        } else {
            split16(g_nf2 + (size_t)nd * 32 + (ks - 6) * 16, true, hA, hB, lA, lB);
        }
        store_group(smc, m, ks, hA, hB, lA, lB);
    }
    stageW(SB + SM_W, g_wimg + WO_N1, WT_N1, t);
    cpasync_wait();
    __syncthreads();

    { float acc[4][2][4];
      init_bias<32, 64>(acc, br1, warp, lane);
      mma_compute<128, 32>(acc, smc, SB, WH_N1, warp, lane);
      __syncthreads();
      epi_split<32, true>(acc, smc, warp, lane);
      stageW(SB + SM_W, g_wimg + WO_N2, WT_N2, t);
      cpasync_wait(); }
    __syncthreads();

    { float acc[8][2][4];
      init_bias<64, 128>(acc, br2, warp, lane);
      mma_compute<64, 64>(acc, smc, SB, WH_N2, warp, lane);
      __syncthreads();
      epi_split<64, true>(acc, smc, warp, lane);
      stageW(SB + SM_W, g_wimg + WO_N3, WT_N3, t);
      cpasync_wait(); }
    __syncthreads();

    { float acc[4][2][4];
      init_bias<32, 64>(acc, br3, warp, lane);
      mma_compute<128, 32>(acc, smc, SB, WH_N3, warp, lane);
      __syncthreads();
      epi_split<32, true>(acc, smc, warp, lane);
      stageW(SB + SM_W, g_wimg + WO_N4, WT_N4, t);
      cpasync_wait(); }
    __syncthreads();

    { // final: 64 -> 64, store f32 to out
        float acc[4][2][4];
        init_bias<32, 64>(acc, br4, warp, lane);
        mma_compute<64, 32>(acc, smc, SB, WH_N4, warp, lane);
        const int m0 = (warp & 3) * 32;
        const int n0 = (warp >> 2) * 32;
        const int rq = lane >> 2, cq = 2 * (lane & 3);
#pragma unroll
        for (int nt = 0; nt < 4; nt++) {
#pragma unroll
            for (int mt = 0; mt < 2; mt++) {
#pragma unroll
                for (int e = 0; e < 4; e++) {
                    int col = n0 + nt * 8 + cq + (e & 1);
                    int row = m0 + mt * 16 + rq + (e >> 1) * 8;
                    if (row < cnt)
                        out[(size_t)(n0g + row) * 64 + col] = acc[nt][mt][e];
                }
            }
        }
    }
}

// ---------------- launch ----------------
extern "C" void kernel_launch(void* const* d_in, const int* in_sizes, int n_in,
                              void* d_out, int out_size) {
    (void)in_sizes; (void)n_in; (void)out_size;
    const float* nf = (const float*)d_in[0];
    const float* ef = (const float*)d_in[1];
    const int* src  = (const int*)d_in[2];
    const int* dst  = (const int*)d_in[3];

    cudaFuncSetAttribute(edge_kernel, cudaFuncAttributeMaxDynamicSharedMemorySize, SMEM_TOT);
    cudaFuncSetAttribute(node_kernel, cudaFuncAttributeMaxDynamicSharedMemorySize, SMEM_TOT);

    prep_kernel<<<128, 256>>>(
        (const float*)d_in[4], (const float*)d_in[6],
        (const float*)d_in[8], (const float*)d_in[10],
        (const float*)d_in[12], (const float*)d_in[14],
        (const float*)d_in[16], (const float*)d_in[18]);
    prep_nf_kernel<<<(NN * 64 + 255) / 256, 256>>>(nf);
    init1_kernel<<<(NN * 32 + 255) / 256, 256>>>();
    init2_kernel<<<(NN * 32 + 255) / 256, 256>>>();

    edge_kernel<<<NE / 128, NTHR, SMEM_TOT>>>(
        ef, src, dst,
        (const float*)d_in[5], (const float*)d_in[7],
        (const float*)d_in[9], (const float*)d_in[11]);

    node_kernel<<<(NN + 127) / 128, NTHR, SMEM_TOT>>>(
        (const float*)d_in[13], (const float*)d_in[15],
        (const float*)d_in[17], (const float*)d_in[19],
        (float*)d_out);
}

// round 16
// speedup vs baseline: 4.0282x; 1.1103x over previous
#include <cuda_runtime.h>
#include <cuda_fp16.h>
#include <math.h>
#include <stdint.h>

#define NN 50000
#define NE 1600000
#define NTHR 256

// ---------------- device scratch ----------------
__device__ float g_nf1[NN * 32];
__device__ float g_nf2[NN * 32];
__device__ __align__(16) __half g_nfh[NN * 64];   // nf fp16 hi
__device__ __align__(16) __half g_nfl[NN * 64];   // nf fp16 lo

// Weight images per layer: [hi padded: Np x (Kr+8) halves, ldmatrix-friendly]
// then [lo: Np rows, paired-u64 layout, stride 136B (K=64) / 288B (K=128/144)].
// E4 is column-PERMUTED: image col j<64 = W col j+1 (features), col 64 = W col 0 (gate).
#define WO_E1 0
#define WO_E2 37888
#define WO_E3 73728
#define WO_E4 109568
#define WO_N1 131968
#define WO_N2 167808
#define WO_N3 203648
#define WO_N4 239488
#define W_IMG_TOTAL 257408
__device__ __align__(16) unsigned char g_wimg[W_IMG_TOTAL];

#define WH_E1 19456
#define WH_E2 18432
#define WH_E3 17408
#define WH_E4 11520
#define WH_N1 17408
#define WH_N2 18432
#define WH_N3 17408
#define WH_N4 9216
#define WT_E1 37888
#define WT_E2 35840
#define WT_E3 35840
#define WT_E4 22400
#define WT_N1 35840
#define WT_N2 35840
#define WT_N3 35840
#define WT_N4 17920

// ---------------- smem layout (bytes) ----------------
#define LDH 152                  // act-hi halves/row (304B, conflict-free ldmatrix)
#define ALB 288                  // act-lo row bytes, paired-u64 layout
#define SM_AH 0                  // 38912
#define SM_AL 38912              // 36864
#define SM_W  75776              // 37888 max
#define SM_DST 113664            // 512
#define SM_SG  114176            // 512
#define SMEM_TOT 114688

// paired-u64 lo layout
__device__ __forceinline__ int lo_off(int k) {
    int ks = k >> 4, w = k & 15;
    return ks * 32 + ((w & 7) >> 1) * 8 + ((w >= 8) ? 4 : 0) + (k & 1) * 2;
}

// ---------------- asm helpers ----------------
__device__ __forceinline__ uint32_t smem_u32(const void* p) {
    uint32_t a;
    asm("{ .reg .u64 t; cvta.to.shared.u64 t, %1; cvt.u32.u64 %0, t; }" : "=r"(a) : "l"(p));
    return a;
}
__device__ __forceinline__ void ldsm4(uint32_t* r, uint32_t addr) {
    asm volatile("ldmatrix.sync.aligned.m8n8.x4.shared.b16 {%0,%1,%2,%3}, [%4];"
                 : "=r"(r[0]), "=r"(r[1]), "=r"(r[2]), "=r"(r[3]) : "r"(addr));
}
__device__ __forceinline__ void ldsm2(uint32_t* r, uint32_t addr) {
    asm volatile("ldmatrix.sync.aligned.m8n8.x2.shared.b16 {%0,%1}, [%2];"
                 : "=r"(r[0]), "=r"(r[1]) : "r"(addr));
}
__device__ __forceinline__ void mma16816(float* d, const uint32_t* a, const uint32_t* b) {
    asm volatile(
        "mma.sync.aligned.m16n8k16.row.col.f32.f16.f16.f32 "
        "{%0,%1,%2,%3}, {%4,%5,%6,%7}, {%8,%9}, {%0,%1,%2,%3};"
        : "+f"(d[0]), "+f"(d[1]), "+f"(d[2]), "+f"(d[3])
        : "r"(a[0]), "r"(a[1]), "r"(a[2]), "r"(a[3]), "r"(b[0]), "r"(b[1]));
}
__device__ __forceinline__ void cpasync16(uint32_t dstS, const void* src) {
    asm volatile("cp.async.cg.shared.global [%0], [%1], 16;"
                 :: "r"(dstS), "l"(src));
}
__device__ __forceinline__ void cpasync_wait() {
    asm volatile("cp.async.commit_group;\n\tcp.async.wait_group 0;" ::: "memory");
}
// vector reduction: g_nf1 pair add (8B aligned)
__device__ __forceinline__ void red2(float* a, float x, float y) {
    asm volatile("red.global.add.v2.f32 [%0], {%1,%2};" :: "l"(a), "f"(x), "f"(y) : "memory");
}

// ---------------- misc ----------------
__device__ __forceinline__ void atomicMaxF(float* a, float v) {
    if (v >= 0.f) atomicMax((int*)a, __float_as_int(v));
    else          atomicMin((unsigned int*)a, (unsigned int)__float_as_int(v));
}
// packed split: hi = f16x2(a,b), lo = f16x2(a-up(a), b-up(b));  lo16 = a-part
__device__ __forceinline__ void split2(float a, float b, uint32_t& hi, uint32_t& lo) {
    asm("cvt.rn.f16x2.f32 %0, %1, %2;" : "=r"(hi) : "f"(b), "f"(a));
    __half2 hh;
    *(uint32_t*)&hh = hi;
    float2 up = __half22float2(hh);
    asm("cvt.rn.f16x2.f32 %0, %1, %2;" : "=r"(lo) : "f"(b - up.y), "f"(a - up.x));
}
__device__ __forceinline__ void split16(const float* p, bool fixinf,
                                        uint4& hA, uint4& hB, uint4& lA, uint4& lB) {
    float v[16];
    const float4* q = (const float4*)p;
    float4 a = q[0], b = q[1], c = q[2], d = q[3];
    v[0]=a.x; v[1]=a.y; v[2]=a.z; v[3]=a.w; v[4]=b.x; v[5]=b.y; v[6]=b.z; v[7]=b.w;
    v[8]=c.x; v[9]=c.y; v[10]=c.z; v[11]=c.w; v[12]=d.x; v[13]=d.y; v[14]=d.z; v[15]=d.w;
    if (fixinf) {
#pragma unroll
        for (int j = 0; j < 16; j++) if (!isfinite(v[j])) v[j] = 0.f;
    }
    uint32_t h[8], l[8];
#pragma unroll
    for (int j = 0; j < 8; j++) split2(v[2 * j], v[2 * j + 1], h[j], l[j]);
    hA = make_uint4(h[0], h[1], h[2], h[3]);
    hB = make_uint4(h[4], h[5], h[6], h[7]);
    lA = make_uint4(l[0], l[1], l[2], l[3]);
    lB = make_uint4(l[4], l[5], l[6], l[7]);
}
__device__ __forceinline__ void store_group(char* smc, int m, int ks,
                                            uint4 hA, uint4 hB, uint4 lA, uint4 lB) {
    *(uint4*)(smc + SM_AH + (m * LDH + ks * 16) * 2) = hA;
    *(uint4*)(smc + SM_AH + (m * LDH + ks * 16) * 2 + 16) = hB;
    *(uint4*)(smc + SM_AL + m * ALB + ks * 32) = make_uint4(lA.x, lB.x, lA.y, lB.y);
    *(uint4*)(smc + SM_AL + m * ALB + ks * 32 + 16) = make_uint4(lA.z, lB.z, lA.w, lB.w);
}
__device__ __forceinline__ void stageW(uint32_t dstS, const unsigned char* src, int bytes, int t) {
    for (int i = t * 16; i < bytes; i += NTHR * 16)
        cpasync16(dstS + i, src + i);
}

// ---------------- core GEMM step: acc += (Ah+Al)x(Wh+Wl), 3-term split ----------------
template<int K, int NW>
__device__ __forceinline__ void mma_step(int k0, float (&acc)[NW / 8][2][4],
                                         uint32_t aH, const char* aL,
                                         uint32_t wH, const char* wL) {
    constexpr int NT = NW / 8;
    constexpr int WLDH = K + 8;
    constexpr int WLBP = (K == 64) ? 136 : 288;
    const int ks32 = (k0 >> 4) * 32;
    uint32_t ah[2][4], al[2][4];
#pragma unroll
    for (int mt = 0; mt < 2; mt++) {
        ldsm4(ah[mt], aH + (uint32_t)(mt * 16 * LDH + k0) * 2);
        uint2 p0 = *(const uint2*)(aL + mt * 16 * ALB + ks32);
        uint2 p1 = *(const uint2*)(aL + (mt * 16 + 8) * ALB + ks32);
        al[mt][0] = p0.x; al[mt][2] = p0.y;
        al[mt][1] = p1.x; al[mt][3] = p1.y;
    }
#pragma unroll
    for (int nt = 0; nt < NT; nt++) {
        uint32_t bh[2], bl[2];
        ldsm2(bh, wH + (uint32_t)(nt * 8 * WLDH + k0) * 2);
        uint2 pb = *(const uint2*)(wL + nt * 8 * WLBP + ks32);
        bl[0] = pb.x; bl[1] = pb.y;
#pragma unroll
        for (int mt = 0; mt < 2; mt++) {
            mma16816(acc[nt][mt], ah[mt], bh);
            mma16816(acc[nt][mt], ah[mt], bl);
            mma16816(acc[nt][mt], al[mt], bh);
        }
    }
}

template<int K, int NW>
__device__ __forceinline__ void mma_compute(float (&acc)[NW / 8][2][4],
                                            const char* smc, uint32_t SB,
                                            int wLoff, int warp, int lane) {
    constexpr int WLDH = K + 8;
    constexpr int WLBP = (K == 64) ? 136 : 288;
    const int m0 = (warp & 3) * 32;
    const int n0 = (warp >> 2) * NW;
    const int arow = m0 + (lane & 7) + ((lane >> 3) & 1) * 8;
    const int acol8 = (lane >> 4) * 8;
    const int brow = lane & 7;
    const int bk8 = ((lane >> 3) & 1) * 8;
    const int rq = lane >> 2, cq = 2 * (lane & 3);
    const int slotB = (cq >> 1) * 8;
    const uint32_t aH = SB + SM_AH + (uint32_t)(arow * LDH + acol8) * 2;
    const char* aL = smc + SM_AL + (m0 + rq) * ALB + slotB;
    const uint32_t wH = SB + SM_W + (uint32_t)((n0 + brow) * WLDH + bk8) * 2;
    const char* wL = smc + SM_W + wLoff + (n0 + rq) * WLBP + slotB;

    if constexpr (NW <= 40) {
#pragma unroll
        for (int k0 = 0; k0 < K; k0 += 16)
            mma_step<K, NW>(k0, acc, aH, aL, wH, wL);
    } else {
#pragma unroll 2
        for (int k0 = 0; k0 < K; k0 += 16)
            mma_step<K, NW>(k0, acc, aH, aL, wH, wL);
    }
}

template<int NW, int NREAL>
__device__ __forceinline__ void init_bias(float (&acc)[NW / 8][2][4],
                                          const float* __restrict__ bias, int warp, int lane) {
    const int n0 = (warp >> 2) * NW;
    const int cq = 2 * (lane & 3);
#pragma unroll
    for (int nt = 0; nt < NW / 8; nt++) {
        int c = n0 + nt * 8 + cq;
        float b0 = (c < NREAL) ? bias[c] : 0.f;
        float b1 = (c + 1 < NREAL) ? bias[c + 1] : 0.f;
#pragma unroll
        for (int mt = 0; mt < 2; mt++) {
            acc[nt][mt][0] = b0; acc[nt][mt][1] = b1;
            acc[nt][mt][2] = b0; acc[nt][mt][3] = b1;
        }
    }
}

// register epilogue: leaky-relu + split + store to act tiles.
// MUST be preceded by __syncthreads().
template<int NW, bool RELU>
__device__ __forceinline__ void epi_split(float (&acc)[NW / 8][2][4],
                                          char* smc, int warp, int lane) {
    const int m0 = (warp & 3) * 32;
    const int n0 = (warp >> 2) * NW;
    const int rq = lane >> 2, cq = 2 * (lane & 3);
#pragma unroll
    for (int nt = 0; nt < NW / 8; nt++) {
#pragma unroll
        for (int mt = 0; mt < 2; mt++) {
            int r = m0 + mt * 16 + rq;
            int c = n0 + nt * 8 + cq;
            float v0 = acc[nt][mt][0], v1 = acc[nt][mt][1];
            float v2 = acc[nt][mt][2], v3 = acc[nt][mt][3];
            if (RELU) {
                v0 = fmaxf(v0, 0.2f * v0); v1 = fmaxf(v1, 0.2f * v1);
                v2 = fmaxf(v2, 0.2f * v2); v3 = fmaxf(v3, 0.2f * v3);
            }
            uint32_t h01, l01, h23, l23;
            split2(v0, v1, h01, l01);
            split2(v2, v3, h23, l23);
            int off = lo_off(c);
            *(uint32_t*)(smc + SM_AH + (r * LDH + c) * 2) = h01;
            *(uint32_t*)(smc + SM_AH + ((r + 8) * LDH + c) * 2) = h23;
            *(uint32_t*)(smc + SM_AL + r * ALB + off) = l01;
            *(uint32_t*)(smc + SM_AL + (r + 8) * ALB + off) = l23;
        }
    }
}

// ---------------- prep / init ----------------
// permE4: image col n<64 = W col n+1 (features), n==64 = W col 0 (gate), else 0
__device__ void fill_layer(int tid, int stride, int baseB, const float* __restrict__ W,
                           int Kr, int Nr, int Np, bool permE4) {
    int Kp = Kr + 8;
    for (int i = tid; i < Np * Kp; i += stride) {
        int n = i / Kp, k = i - n * Kp;
        int sc = permE4 ? ((n < 64) ? n + 1 : ((n == 64) ? 0 : -1)) : n;
        float v = (k < Kr && sc >= 0 && sc < Nr) ? W[k * Nr + sc] : 0.f;
        *(__half*)(g_wimg + baseB + i * 2) = __float2half_rn(v);
    }
    int loB = baseB + Np * Kp * 2;
    int strideB = (Kr == 64) ? 136 : 288;
    for (int i = tid; i < Np * Kr; i += stride) {
        int n = i / Kr, k = i - n * Kr;
        int sc = permE4 ? ((n < 64) ? n + 1 : ((n == 64) ? 0 : -1)) : n;
        float v = (sc >= 0 && sc < Nr) ? W[k * Nr + sc] : 0.f;
        __half h = __float2half_rn(v);
        __half l = __float2half_rn(v - __half2float(h));
        *(__half*)(g_wimg + loB + n * strideB + lo_off(k)) = l;
    }
}

extern "C" __global__ void prep_kernel(const float* Wm1, const float* Wm2,
                                       const float* Wm3, const float* Wm4,
                                       const float* Wr1, const float* Wr2,
                                       const float* Wr3, const float* Wr4) {
    int tid = blockIdx.x * blockDim.x + threadIdx.x;
    int stride = gridDim.x * blockDim.x;
    fill_layer(tid, stride, WO_E1, Wm1, 144, 64, 64, false);
    fill_layer(tid, stride, WO_E2, Wm2, 64, 128, 128, false);
    fill_layer(tid, stride, WO_E3, Wm3, 128, 64, 64, false);
    fill_layer(tid, stride, WO_E4, Wm4, 64, 65, 80, true);
    fill_layer(tid, stride, WO_N1, Wr1, 128, 64, 64, false);
    fill_layer(tid, stride, WO_N2, Wr2, 64, 128, 128, false);
    fill_layer(tid, stride, WO_N3, Wr3, 128, 64, 64, false);
    fill_layer(tid, stride, WO_N4, Wr4, 64, 64, 64, false);
}

extern "C" __global__ void prep_nf_kernel(const float* __restrict__ nf) {
    int i = blockIdx.x * blockDim.x + threadIdx.x;
    if (i < NN * 64) {
        float v = nf[i];
        __half h = __float2half_rn(v);
        g_nfh[i] = h;
        g_nfl[i] = __float2half_rn(v - __half2float(h));
    }
}

extern "C" __global__ void init_kernel() {
    int i = blockIdx.x * blockDim.x + threadIdx.x;
    if (i < NN * 32) { g_nf1[i] = 0.f; g_nf2[i] = -INFINITY; }
}

// ---------------- edge kernel ----------------
extern "C" __global__ void __launch_bounds__(NTHR, 2)
edge_kernel(const float* __restrict__ ef,
            const int* __restrict__ src, const int* __restrict__ dst,
            const float* __restrict__ bm1, const float* __restrict__ bm2,
            const float* __restrict__ bm3, const float* __restrict__ bm4) {
    extern __shared__ char smc[];
    const uint32_t SB = smem_u32(smc);
    int* sdst = (int*)(smc + SM_DST);
    float* sg = (float*)(smc + SM_SG);
    const int t = threadIdx.x, warp = t >> 5, lane = t & 31;
    const int e0 = blockIdx.x * 128;

    if (t < 128) sdst[t] = dst[e0 + t];

    // gather X = [nf[src](presplit) | nf[dst](presplit) | ef(runtime split)]
    for (int idx = t; idx < 128 * 9; idx += NTHR) {
        int m = idx / 9, ks = idx - m * 9;
        uint4 hA, hB, lA, lB;
        if (ks < 8) {
            int node = (ks < 4) ? src[e0 + m] : dst[e0 + m];
            int k16 = (ks & 3) * 16;
            const uint4* ph = (const uint4*)(g_nfh + (size_t)node * 64 + k16);
            const uint4* pl = (const uint4*)(g_nfl + (size_t)node * 64 + k16);
            hA = ph[0]; hB = ph[1]; lA = pl[0]; lB = pl[1];
        } else {
            split16(ef + (size_t)(e0 + m) * 16, false, hA, hB, lA, lB);
        }
        store_group(smc, m, ks, hA, hB, lA, lB);
    }
    stageW(SB + SM_W, g_wimg + WO_E1, WT_E1, t);
    cpasync_wait();
    __syncthreads();

    { // L1: 144 -> 64
        float acc[4][2][4];
        init_bias<32, 64>(acc, bm1, warp, lane);
        mma_compute<144, 32>(acc, smc, SB, WH_E1, warp, lane);
        __syncthreads();
        epi_split<32, true>(acc, smc, warp, lane);
        stageW(SB + SM_W, g_wimg + WO_E2, WT_E2, t);
        cpasync_wait();
    }
    __syncthreads();

    { // L2: 64 -> 128
        float acc[8][2][4];
        init_bias<64, 128>(acc, bm2, warp, lane);
        mma_compute<64, 64>(acc, smc, SB, WH_E2, warp, lane);
        __syncthreads();
        epi_split<64, true>(acc, smc, warp, lane);
        stageW(SB + SM_W, g_wimg + WO_E3, WT_E3, t);
        cpasync_wait();
    }
    __syncthreads();

    { // L3: 128 -> 64
        float acc[4][2][4];
        init_bias<32, 64>(acc, bm3, warp, lane);
        mma_compute<128, 32>(acc, smc, SB, WH_E3, warp, lane);
        __syncthreads();
        epi_split<32, true>(acc, smc, warp, lane);
        stageW(SB + SM_W, g_wimg + WO_E4, WT_E4, t);
        cpasync_wait();
    }
    __syncthreads();

    { // L4 (permuted): cols 0..63 = gated features, col 64 = gate logit
        float acc[5][2][4];
        init_bias<40, 64>(acc, bm4 + 1, warp, lane);   // features bias; col>=64 -> 0
        mma_compute<64, 40>(acc, smc, SB, WH_E4, warp, lane);

        const int m0 = (warp & 3) * 32;
        const int n0 = (warp >> 2) * 40;
        const int rq = lane >> 2, cq = 2 * (lane & 3);
        // gate col 64 = n0(40) + nt3*8 + cq0, handled by warps 4..7
        if ((warp >> 2) == 1 && (lane & 3) == 0) {
            float b0 = bm4[0];
#pragma unroll
            for (int mt = 0; mt < 2; mt++) {
                int r = m0 + mt * 16 + rq;
                sg[r] = 1.f / (1.f + expf(-(acc[3][mt][0] + b0)));
                sg[r + 8] = 1.f / (1.f + expf(-(acc[3][mt][2] + b0)));
            }
        }
        __syncthreads();
        // scatter: cols 0..31 -> vector sum, 32..63 -> scalar max
#pragma unroll
        for (int nt = 0; nt < 5; nt++) {
            int c = n0 + nt * 8 + cq;           // even
            if (c < 64) {
#pragma unroll
                for (int mt = 0; mt < 2; mt++) {
#pragma unroll
                    for (int half = 0; half < 2; half++) {
                        int row = m0 + mt * 16 + rq + half * 8;
                        float g = sg[row];
                        int d = sdst[row];
                        float vx = acc[nt][mt][half * 2] * g;
                        float vy = acc[nt][mt][half * 2 + 1] * g;
                        if (c < 32) {
                            red2(&g_nf1[d * 32 + c], vx, vy);
                        } else {
                            atomicMaxF(&g_nf2[d * 32 + c - 32], vx);
                            atomicMaxF(&g_nf2[d * 32 + c - 31], vy);
                        }
                    }
                }
            }
        }
    }
}

// ---------------- node kernel ----------------
extern "C" __global__ void __launch_bounds__(NTHR, 2)
node_kernel(const float* __restrict__ br1, const float* __restrict__ br2,
            const float* __restrict__ br3, const float* __restrict__ br4,
            float* __restrict__ out) {
    extern __shared__ char smc[];
    const uint32_t SB = smem_u32(smc);
    const int t = threadIdx.x, warp = t >> 5, lane = t & 31;
    const int n0g = blockIdx.x * 128;
    const int cnt = min(128, NN - n0g);

    // gather Y = [nf(presplit) | nf1(split) | nf2(split+fix)]
    for (int idx = t; idx < 128 * 8; idx += NTHR) {
        int m = idx >> 3, ks = idx & 7;
        int nd = n0g + min(m, cnt - 1);
        uint4 hA, hB, lA, lB;
        if (ks < 4) {
            const uint4* ph = (const uint4*)(g_nfh + (size_t)nd * 64 + ks * 16);
            const uint4* pl = (const uint4*)(g_nfl + (size_t)nd * 64 + ks * 16);
            hA = ph[0]; hB = ph[1]; lA = pl[0]; lB = pl[1];
        } else if (ks < 6) {
            split16(g_nf1 + (size_t)nd * 32 + (ks - 4) * 16, false, hA, hB, lA, lB);
        } else {
            split16(g_nf2 + (size_t)nd * 32 + (ks - 6) * 16, true, hA, hB, lA, lB);
        }
        store_group(smc, m, ks, hA, hB, lA, lB);
    }
    stageW(SB + SM_W, g_wimg + WO_N1, WT_N1, t);
    cpasync_wait();
    __syncthreads();

    { float acc[4][2][4];
      init_bias<32, 64>(acc, br1, warp, lane);
      mma_compute<128, 32>(acc, smc, SB, WH_N1, warp, lane);
      __syncthreads();
      epi_split<32, true>(acc, smc, warp, lane);
      stageW(SB + SM_W, g_wimg + WO_N2, WT_N2, t);
      cpasync_wait(); }
    __syncthreads();

    { float acc[8][2][4];
      init_bias<64, 128>(acc, br2, warp, lane);
      mma_compute<64, 64>(acc, smc, SB, WH_N2, warp, lane);
      __syncthreads();
      epi_split<64, true>(acc, smc, warp, lane);
      stageW(SB + SM_W, g_wimg + WO_N3, WT_N3, t);
      cpasync_wait(); }
    __syncthreads();

    { float acc[4][2][4];
      init_bias<32, 64>(acc, br3, warp, lane);
      mma_compute<128, 32>(acc, smc, SB, WH_N3, warp, lane);
      __syncthreads();
      epi_split<32, true>(acc, smc, warp, lane);
      stageW(SB + SM_W, g_wimg + WO_N4, WT_N4, t);
      cpasync_wait(); }
    __syncthreads();

    { // final: 64 -> 64, store f32 to out
        float acc[4][2][4];
        init_bias<32, 64>(acc, br4, warp, lane);
        mma_compute<64, 32>(acc, smc, SB, WH_N4, warp, lane);
        const int m0 = (warp & 3) * 32;
        const int n0 = (warp >> 2) * 32;
        const int rq = lane >> 2, cq = 2 * (lane & 3);
#pragma unroll
        for (int nt = 0; nt < 4; nt++) {
#pragma unroll
            for (int mt = 0; mt < 2; mt++) {
#pragma unroll
                for (int e = 0; e < 4; e++) {
                    int col = n0 + nt * 8 + cq + (e & 1);
                    int row = m0 + mt * 16 + rq + (e >> 1) * 8;
                    if (row < cnt)
                        out[(size_t)(n0g + row) * 64 + col] = acc[nt][mt][e];
                }
            }
        }
    }
}

// ---------------- launch ----------------
extern "C" void kernel_launch(void* const* d_in, const int* in_sizes, int n_in,
                              void* d_out, int out_size) {
    (void)in_sizes; (void)n_in; (void)out_size;
    const float* nf = (const float*)d_in[0];
    const float* ef = (const float*)d_in[1];
    const int* src  = (const int*)d_in[2];
    const int* dst  = (const int*)d_in[3];

    cudaFuncSetAttribute(edge_kernel, cudaFuncAttributeMaxDynamicSharedMemorySize, SMEM_TOT);
    cudaFuncSetAttribute(node_kernel, cudaFuncAttributeMaxDynamicSharedMemorySize, SMEM_TOT);

    prep_kernel<<<128, 256>>>(
        (const float*)d_in[4], (const float*)d_in[6],
        (const float*)d_in[8], (const float*)d_in[10],
        (const float*)d_in[12], (const float*)d_in[14],
        (const float*)d_in[16], (const float*)d_in[18]);
    prep_nf_kernel<<<(NN * 64 + 255) / 256, 256>>>(nf);
    init_kernel<<<(NN * 32 + 255) / 256, 256>>>();

    edge_kernel<<<NE / 128, NTHR, SMEM_TOT>>>(
        ef, src, dst,
        (const float*)d_in[5], (const float*)d_in[7],
        (const float*)d_in[9], (const float*)d_in[11]);

    node_kernel<<<(NN + 127) / 128, NTHR, SMEM_TOT>>>(
        (const float*)d_in[13], (const float*)d_in[15],
        (const float*)d_in[17], (const float*)d_in[19],
        (float*)d_out);
}

// round 17
// speedup vs baseline: 5.7793x; 1.4347x over previous
#include <cuda_runtime.h>
#include <cuda_fp16.h>
#include <math.h>
#include <stdint.h>

#define NN 50000
#define NE 1600000
#define NTHR 256

// ---------------- device scratch ----------------
__device__ float g_nf1[NN * 32];
__device__ float g_nf2[NN * 32];
__device__ __align__(16) __half g_nfh[NN * 64];   // nf fp16 (hi)

// Weight images per layer: [hi padded: Np x (Kr+8) halves, ldmatrix-friendly]
// then [lo: Np rows, paired-u64 layout, stride 136B (K=64) / 288B (K=128/144)].
// E4 is column-PERMUTED: image col j<64 = W col j+1 (features), col 64 = W col 0 (gate).
#define WO_E1 0
#define WO_E2 37888
#define WO_E3 73728
#define WO_E4 109568
#define WO_N1 131968
#define WO_N2 167808
#define WO_N3 203648
#define WO_N4 239488
#define W_IMG_TOTAL 257408
__device__ __align__(16) unsigned char g_wimg[W_IMG_TOTAL];

#define WH_E1 19456
#define WH_E2 18432
#define WH_E3 17408
#define WH_E4 11520
#define WH_N1 17408
#define WH_N2 18432
#define WH_N3 17408
#define WH_N4 9216
#define WT_E1 37888
#define WT_E2 35840
#define WT_E3 35840
#define WT_E4 22400
#define WT_N1 35840
#define WT_N2 35840
#define WT_N3 35840
#define WT_N4 17920

// ---------------- smem layout (bytes) ----------------
#define LDH 152                  // act halves/row (304B = 19x16B, conflict-free)
#define SM_AH 0                  // 128*304 = 38912
#define SM_W  38912              // 37888 max
#define SM_DST 76800             // 512
#define SM_SG  77312             // 512
#define SMEM_TOT 77824

// paired-u64 lo layout (weights only)
__device__ __forceinline__ int lo_off(int k) {
    int ks = k >> 4, w = k & 15;
    return ks * 32 + ((w & 7) >> 1) * 8 + ((w >= 8) ? 4 : 0) + (k & 1) * 2;
}

// ---------------- asm helpers ----------------
__device__ __forceinline__ uint32_t smem_u32(const void* p) {
    uint32_t a;
    asm("{ .reg .u64 t; cvta.to.shared.u64 t, %1; cvt.u32.u64 %0, t; }" : "=r"(a) : "l"(p));
    return a;
}
__device__ __forceinline__ void ldsm4(uint32_t* r, uint32_t addr) {
    asm volatile("ldmatrix.sync.aligned.m8n8.x4.shared.b16 {%0,%1,%2,%3}, [%4];"
                 : "=r"(r[0]), "=r"(r[1]), "=r"(r[2]), "=r"(r[3]) : "r"(addr));
}
__device__ __forceinline__ void ldsm2(uint32_t* r, uint32_t addr) {
    asm volatile("ldmatrix.sync.aligned.m8n8.x2.shared.b16 {%0,%1}, [%2];"
                 : "=r"(r[0]), "=r"(r[1]) : "r"(addr));
}
__device__ __forceinline__ void mma16816(float* d, const uint32_t* a, const uint32_t* b) {
    asm volatile(
        "mma.sync.aligned.m16n8k16.row.col.f32.f16.f16.f32 "
        "{%0,%1,%2,%3}, {%4,%5,%6,%7}, {%8,%9}, {%0,%1,%2,%3};"
        : "+f"(d[0]), "+f"(d[1]), "+f"(d[2]), "+f"(d[3])
        : "r"(a[0]), "r"(a[1]), "r"(a[2]), "r"(a[3]), "r"(b[0]), "r"(b[1]));
}
__device__ __forceinline__ void cpasync16(uint32_t dstS, const void* src) {
    asm volatile("cp.async.cg.shared.global [%0], [%1], 16;"
                 :: "r"(dstS), "l"(src));
}
__device__ __forceinline__ void cpasync_wait() {
    asm volatile("cp.async.commit_group;\n\tcp.async.wait_group 0;" ::: "memory");
}
__device__ __forceinline__ void red2(float* a, float x, float y) {
    asm volatile("red.global.add.v2.f32 [%0], {%1,%2};" :: "l"(a), "f"(x), "f"(y) : "memory");
}

// ---------------- misc ----------------
__device__ __forceinline__ void atomicMaxF(float* a, float v) {
    if (v >= 0.f) atomicMax((int*)a, __float_as_int(v));
    else          atomicMin((unsigned int*)a, (unsigned int)__float_as_int(v));
}
__device__ __forceinline__ uint32_t cvt2(float a, float b) {
    uint32_t r;
    asm("cvt.rn.f16x2.f32 %0, %1, %2;" : "=r"(r) : "f"(b), "f"(a));
    return r;
}
// convert 16 f32 -> 8 packed f16x2 (two uint4)
__device__ __forceinline__ void cvt16(const float* p, bool fixinf, uint4& hA, uint4& hB) {
    float v[16];
    const float4* q = (const float4*)p;
    float4 a = q[0], b = q[1], c = q[2], d = q[3];
    v[0]=a.x; v[1]=a.y; v[2]=a.z; v[3]=a.w; v[4]=b.x; v[5]=b.y; v[6]=b.z; v[7]=b.w;
    v[8]=c.x; v[9]=c.y; v[10]=c.z; v[11]=c.w; v[12]=d.x; v[13]=d.y; v[14]=d.z; v[15]=d.w;
    if (fixinf) {
#pragma unroll
        for (int j = 0; j < 16; j++) if (!isfinite(v[j])) v[j] = 0.f;
    }
    hA = make_uint4(cvt2(v[0], v[1]), cvt2(v[2], v[3]), cvt2(v[4], v[5]), cvt2(v[6], v[7]));
    hB = make_uint4(cvt2(v[8], v[9]), cvt2(v[10], v[11]), cvt2(v[12], v[13]), cvt2(v[14], v[15]));
}
__device__ __forceinline__ void stageW(uint32_t dstS, const unsigned char* src, int bytes, int t) {
    for (int i = t * 16; i < bytes; i += NTHR * 16)
        cpasync16(dstS + i, src + i);
}

// ---------------- core GEMM step: acc += Ah x (Wh + Wl), 2-term split ----------------
template<int K, int NW>
__device__ __forceinline__ void mma_step(int k0, float (&acc)[NW / 8][2][4],
                                         uint32_t aH, uint32_t wH, const char* wL) {
    constexpr int NT = NW / 8;
    constexpr int WLDH = K + 8;
    constexpr int WLBP = (K == 64) ? 136 : 288;
    const int ks32 = (k0 >> 4) * 32;
    uint32_t ah[2][4];
#pragma unroll
    for (int mt = 0; mt < 2; mt++)
        ldsm4(ah[mt], aH + (uint32_t)(mt * 16 * LDH + k0) * 2);
#pragma unroll
    for (int nt = 0; nt < NT; nt++) {
        uint32_t bh[2], bl[2];
        ldsm2(bh, wH + (uint32_t)(nt * 8 * WLDH + k0) * 2);
        uint2 pb = *(const uint2*)(wL + nt * 8 * WLBP + ks32);
        bl[0] = pb.x; bl[1] = pb.y;
#pragma unroll
        for (int mt = 0; mt < 2; mt++) {
            mma16816(acc[nt][mt], ah[mt], bh);
            mma16816(acc[nt][mt], ah[mt], bl);
        }
    }
}

template<int K, int NW>
__device__ __forceinline__ void mma_compute(float (&acc)[NW / 8][2][4],
                                            const char* smc, uint32_t SB,
                                            int wLoff, int warp, int lane) {
    constexpr int WLDH = K + 8;
    constexpr int WLBP = (K == 64) ? 136 : 288;
    const int m0 = (warp & 3) * 32;
    const int n0 = (warp >> 2) * NW;
    const int arow = m0 + (lane & 7) + ((lane >> 3) & 1) * 8;
    const int acol8 = (lane >> 4) * 8;
    const int brow = lane & 7;
    const int bk8 = ((lane >> 3) & 1) * 8;
    const int rq = lane >> 2, cq = 2 * (lane & 3);
    const int slotB = (cq >> 1) * 8;
    const uint32_t aH = SB + SM_AH + (uint32_t)(arow * LDH + acol8) * 2;
    const uint32_t wH = SB + SM_W + (uint32_t)((n0 + brow) * WLDH + bk8) * 2;
    const char* wL = smc + SM_W + wLoff + (n0 + rq) * WLBP + slotB;

#pragma unroll
    for (int k0 = 0; k0 < K; k0 += 16)
        mma_step<K, NW>(k0, acc, aH, wH, wL);
}

template<int NW, int NREAL>
__device__ __forceinline__ void init_bias(float (&acc)[NW / 8][2][4],
                                          const float* __restrict__ bias, int warp, int lane) {
    const int n0 = (warp >> 2) * NW;
    const int cq = 2 * (lane & 3);
#pragma unroll
    for (int nt = 0; nt < NW / 8; nt++) {
        int c = n0 + nt * 8 + cq;
        float b0 = (c < NREAL) ? bias[c] : 0.f;
        float b1 = (c + 1 < NREAL) ? bias[c + 1] : 0.f;
#pragma unroll
        for (int mt = 0; mt < 2; mt++) {
            acc[nt][mt][0] = b0; acc[nt][mt][1] = b1;
            acc[nt][mt][2] = b0; acc[nt][mt][3] = b1;
        }
    }
}

// register epilogue: leaky-relu + fp16 convert + store to act tile.
// MUST be preceded by __syncthreads().
template<int NW, bool RELU>
__device__ __forceinline__ void epi_store(float (&acc)[NW / 8][2][4],
                                          char* smc, int warp, int lane) {
    const int m0 = (warp & 3) * 32;
    const int n0 = (warp >> 2) * NW;
    const int rq = lane >> 2, cq = 2 * (lane & 3);
#pragma unroll
    for (int nt = 0; nt < NW / 8; nt++) {
#pragma unroll
        for (int mt = 0; mt < 2; mt++) {
            int r = m0 + mt * 16 + rq;
            int c = n0 + nt * 8 + cq;
            float v0 = acc[nt][mt][0], v1 = acc[nt][mt][1];
            float v2 = acc[nt][mt][2], v3 = acc[nt][mt][3];
            if (RELU) {
                v0 = fmaxf(v0, 0.2f * v0); v1 = fmaxf(v1, 0.2f * v1);
                v2 = fmaxf(v2, 0.2f * v2); v3 = fmaxf(v3, 0.2f * v3);
            }
            *(uint32_t*)(smc + SM_AH + (r * LDH + c) * 2) = cvt2(v0, v1);
            *(uint32_t*)(smc + SM_AH + ((r + 8) * LDH + c) * 2) = cvt2(v2, v3);
        }
    }
}

// ---------------- prep / init ----------------
__device__ void fill_layer(int tid, int stride, int baseB, const float* __restrict__ W,
                           int Kr, int Nr, int Np, bool permE4) {
    int Kp = Kr + 8;
    for (int i = tid; i < Np * Kp; i += stride) {
        int n = i / Kp, k = i - n * Kp;
        int sc = permE4 ? ((n < 64) ? n + 1 : ((n == 64) ? 0 : -1)) : n;
        float v = (k < Kr && sc >= 0 && sc < Nr) ? W[k * Nr + sc] : 0.f;
        *(__half*)(g_wimg + baseB + i * 2) = __float2half_rn(v);
    }
    int loB = baseB + Np * Kp * 2;
    int strideB = (Kr == 64) ? 136 : 288;
    for (int i = tid; i < Np * Kr; i += stride) {
        int n = i / Kr, k = i - n * Kr;
        int sc = permE4 ? ((n < 64) ? n + 1 : ((n == 64) ? 0 : -1)) : n;
        float v = (sc >= 0 && sc < Nr) ? W[k * Nr + sc] : 0.f;
        __half h = __float2half_rn(v);
        __half l = __float2half_rn(v - __half2float(h));
        *(__half*)(g_wimg + loB + n * strideB + lo_off(k)) = l;
    }
}

extern "C" __global__ void prep_kernel(const float* Wm1, const float* Wm2,
                                       const float* Wm3, const float* Wm4,
                                       const float* Wr1, const float* Wr2,
                                       const float* Wr3, const float* Wr4) {
    int tid = blockIdx.x * blockDim.x + threadIdx.x;
    int stride = gridDim.x * blockDim.x;
    fill_layer(tid, stride, WO_E1, Wm1, 144, 64, 64, false);
    fill_layer(tid, stride, WO_E2, Wm2, 64, 128, 128, false);
    fill_layer(tid, stride, WO_E3, Wm3, 128, 64, 64, false);
    fill_layer(tid, stride, WO_E4, Wm4, 64, 65, 80, true);
    fill_layer(tid, stride, WO_N1, Wr1, 128, 64, 64, false);
    fill_layer(tid, stride, WO_N2, Wr2, 64, 128, 128, false);
    fill_layer(tid, stride, WO_N3, Wr3, 128, 64, 64, false);
    fill_layer(tid, stride, WO_N4, Wr4, 64, 64, 64, false);
}

extern "C" __global__ void prep_nf_kernel(const float* __restrict__ nf) {
    int i = blockIdx.x * blockDim.x + threadIdx.x;
    if (i < NN * 64) g_nfh[i] = __float2half_rn(nf[i]);
}

extern "C" __global__ void init_kernel() {
    int i = blockIdx.x * blockDim.x + threadIdx.x;
    if (i < NN * 32) { g_nf1[i] = 0.f; g_nf2[i] = -INFINITY; }
}

// ---------------- edge kernel ----------------
extern "C" __global__ void __launch_bounds__(NTHR, 2)
edge_kernel(const float* __restrict__ ef,
            const int* __restrict__ src, const int* __restrict__ dst,
            const float* __restrict__ bm1, const float* __restrict__ bm2,
            const float* __restrict__ bm3, const float* __restrict__ bm4) {
    extern __shared__ char smc[];
    const uint32_t SB = smem_u32(smc);
    int* sdst = (int*)(smc + SM_DST);
    float* sg = (float*)(smc + SM_SG);
    const int t = threadIdx.x, warp = t >> 5, lane = t & 31;
    const int e0 = blockIdx.x * 128;

    if (t < 128) sdst[t] = dst[e0 + t];

    // gather X = [nf[src] | nf[dst] | ef->f16] via cp.async (nf) + convert (ef)
    for (int idx = t; idx < 128 * 8; idx += NTHR) {
        int m = idx >> 3, ks = idx & 7;
        int node = (ks < 4) ? src[e0 + m] : dst[e0 + m];
        const __half* p = g_nfh + (size_t)node * 64 + (ks & 3) * 16;
        uint32_t d = SB + SM_AH + (uint32_t)(m * LDH + ks * 16) * 2;
        cpasync16(d, p);
        cpasync16(d + 16, p + 8);
    }
    for (int idx = t; idx < 128; idx += NTHR) {
        uint4 hA, hB;
        cvt16(ef + (size_t)(e0 + idx) * 16, false, hA, hB);
        *(uint4*)(smc + SM_AH + (idx * LDH + 128) * 2) = hA;
        *(uint4*)(smc + SM_AH + (idx * LDH + 128) * 2 + 16) = hB;
    }
    stageW(SB + SM_W, g_wimg + WO_E1, WT_E1, t);
    cpasync_wait();
    __syncthreads();

    { // L1: 144 -> 64
        float acc[4][2][4];
        init_bias<32, 64>(acc, bm1, warp, lane);
        mma_compute<144, 32>(acc, smc, SB, WH_E1, warp, lane);
        __syncthreads();
        epi_store<32, true>(acc, smc, warp, lane);
        stageW(SB + SM_W, g_wimg + WO_E2, WT_E2, t);
        cpasync_wait();
    }
    __syncthreads();

    { // L2: 64 -> 128
        float acc[8][2][4];
        init_bias<64, 128>(acc, bm2, warp, lane);
        mma_compute<64, 64>(acc, smc, SB, WH_E2, warp, lane);
        __syncthreads();
        epi_store<64, true>(acc, smc, warp, lane);
        stageW(SB + SM_W, g_wimg + WO_E3, WT_E3, t);
        cpasync_wait();
    }
    __syncthreads();

    { // L3: 128 -> 64
        float acc[4][2][4];
        init_bias<32, 64>(acc, bm3, warp, lane);
        mma_compute<128, 32>(acc, smc, SB, WH_E3, warp, lane);
        __syncthreads();
        epi_store<32, true>(acc, smc, warp, lane);
        stageW(SB + SM_W, g_wimg + WO_E4, WT_E4, t);
        cpasync_wait();
    }
    __syncthreads();

    { // L4 (permuted): cols 0..63 = gated features, col 64 = gate logit
        float acc[5][2][4];
        init_bias<40, 64>(acc, bm4 + 1, warp, lane);   // features bias; col>=64 -> 0
        mma_compute<64, 40>(acc, smc, SB, WH_E4, warp, lane);

        const int m0 = (warp & 3) * 32;
        const int n0 = (warp >> 2) * 40;
        const int rq = lane >> 2, cq = 2 * (lane & 3);
        if ((warp >> 2) == 1 && (lane & 3) == 0) {
            float b0 = bm4[0];
#pragma unroll
            for (int mt = 0; mt < 2; mt++) {
                int r = m0 + mt * 16 + rq;
                sg[r] = 1.f / (1.f + expf(-(acc[3][mt][0] + b0)));
                sg[r + 8] = 1.f / (1.f + expf(-(acc[3][mt][2] + b0)));
            }
        }
        __syncthreads();
        // scatter: cols 0..31 -> vector sum, 32..63 -> scalar max
#pragma unroll
        for (int nt = 0; nt < 5; nt++) {
            int c = n0 + nt * 8 + cq;           // even
            if (c < 64) {
#pragma unroll
                for (int mt = 0; mt < 2; mt++) {
#pragma unroll
                    for (int half = 0; half < 2; half++) {
                        int row = m0 + mt * 16 + rq + half * 8;
                        float g = sg[row];
                        int d = sdst[row];
                        float vx = acc[nt][mt][half * 2] * g;
                        float vy = acc[nt][mt][half * 2 + 1] * g;
                        if (c < 32) {
                            red2(&g_nf1[d * 32 + c], vx, vy);
                        } else {
                            atomicMaxF(&g_nf2[d * 32 + c - 32], vx);
                            atomicMaxF(&g_nf2[d * 32 + c - 31], vy);
                        }
                    }
                }
            }
        }
    }
}

// ---------------- node kernel ----------------
extern "C" __global__ void __launch_bounds__(NTHR, 2)
node_kernel(const float* __restrict__ br1, const float* __restrict__ br2,
            const float* __restrict__ br3, const float* __restrict__ br4,
            float* __restrict__ out) {
    extern __shared__ char smc[];
    const uint32_t SB = smem_u32(smc);
    const int t = threadIdx.x, warp = t >> 5, lane = t & 31;
    const int n0g = blockIdx.x * 128;
    const int cnt = min(128, NN - n0g);

    // gather Y = [nf (cp.async) | nf1->f16 | nf2->f16(fix)]
    for (int idx = t; idx < 128 * 4; idx += NTHR) {
        int m = idx >> 2, ks = idx & 3;
        int nd = n0g + min(m, cnt - 1);
        const __half* p = g_nfh + (size_t)nd * 64 + ks * 16;
        uint32_t d = SB + SM_AH + (uint32_t)(m * LDH + ks * 16) * 2;
        cpasync16(d, p);
        cpasync16(d + 16, p + 8);
    }
    for (int idx = t; idx < 128 * 4; idx += NTHR) {
        int m = idx >> 2, ks = idx & 3;
        int nd = n0g + min(m, cnt - 1);
        uint4 hA, hB;
        if (ks < 2) cvt16(g_nf1 + (size_t)nd * 32 + ks * 16, false, hA, hB);
        else        cvt16(g_nf2 + (size_t)nd * 32 + (ks - 2) * 16, true, hA, hB);
        uint32_t off = (m * LDH + 64 + ks * 16) * 2;
        *(uint4*)(smc + SM_AH + off) = hA;
        *(uint4*)(smc + SM_AH + off + 16) = hB;
    }
    stageW(SB + SM_W, g_wimg + WO_N1, WT_N1, t);
    cpasync_wait();
    __syncthreads();

    { float acc[4][2][4];
      init_bias<32, 64>(acc, br1, warp, lane);
      mma_compute<128, 32>(acc, smc, SB, WH_N1, warp, lane);
      __syncthreads();
      epi_store<32, true>(acc, smc, warp, lane);
      stageW(SB + SM_W, g_wimg + WO_N2, WT_N2, t);
      cpasync_wait(); }
    __syncthreads();

    { float acc[8][2][4];
      init_bias<64, 128>(acc, br2, warp, lane);
      mma_compute<64, 64>(acc, smc, SB, WH_N2, warp, lane);
      __syncthreads();
      epi_store<64, true>(acc, smc, warp, lane);
      stageW(SB + SM_W, g_wimg + WO_N3, WT_N3, t);
      cpasync_wait(); }
    __syncthreads();

    { float acc[4][2][4];
      init_bias<32, 64>(acc, br3, warp, lane);
      mma_compute<128, 32>(acc, smc, SB, WH_N3, warp, lane);
      __syncthreads();
      epi_store<32, true>(acc, smc, warp, lane);
      stageW(SB + SM_W, g_wimg + WO_N4, WT_N4, t);
      cpasync_wait(); }
    __syncthreads();

    { // final: 64 -> 64, store f32 to out
        float acc[4][2][4];
        init_bias<32, 64>(acc, br4, warp, lane);
        mma_compute<64, 32>(acc, smc, SB, WH_N4, warp, lane);
        const int m0 = (warp & 3) * 32;
        const int n0 = (warp >> 2) * 32;
        const int rq = lane >> 2, cq = 2 * (lane & 3);
#pragma unroll
        for (int nt = 0; nt < 4; nt++) {
#pragma unroll
            for (int mt = 0; mt < 2; mt++) {
#pragma unroll
                for (int e = 0; e < 4; e++) {
                    int col = n0 + nt * 8 + cq + (e & 1);
                    int row = m0 + mt * 16 + rq + (e >> 1) * 8;
                    if (row < cnt)
                        out[(size_t)(n0g + row) * 64 + col] = acc[nt][mt][e];
                }
            }
        }
    }
}

// ---------------- launch ----------------
extern "C" void kernel_launch(void* const* d_in, const int* in_sizes, int n_in,
                              void* d_out, int out_size) {
    (void)in_sizes; (void)n_in; (void)out_size;
    const float* nf = (const float*)d_in[0];
    const float* ef = (const float*)d_in[1];
    const int* src  = (const int*)d_in[2];
    const int* dst  = (const int*)d_in[3];

    cudaFuncSetAttribute(edge_kernel, cudaFuncAttributeMaxDynamicSharedMemorySize, SMEM_TOT);
    cudaFuncSetAttribute(node_kernel, cudaFuncAttributeMaxDynamicSharedMemorySize, SMEM_TOT);

    prep_kernel<<<128, 256>>>(
        (const float*)d_in[4], (const float*)d_in[6],
        (const float*)d_in[8], (const float*)d_in[10],
        (const float*)d_in[12], (const float*)d_in[14],
        (const float*)d_in[16], (const float*)d_in[18]);
    prep_nf_kernel<<<(NN * 64 + 255) / 256, 256>>>(nf);
    init_kernel<<<(NN * 32 + 255) / 256, 256>>>();

    edge_kernel<<<NE / 128, NTHR, SMEM_TOT>>>(
        ef, src, dst,
        (const float*)d_in[5], (const float*)d_in[7],
        (const float*)d_in[9], (const float*)d_in[11]);

    node_kernel<<<(NN + 127) / 128, NTHR, SMEM_TOT>>>(
        (const float*)d_in[13], (const float*)d_in[15],
        (const float*)d_in[17], (const float*)d_in[19],
        (float*)d_out);
}